// round 3
// baseline (speedup 1.0000x reference)
#include <cuda_runtime.h>
#include <math.h>
#include <stdint.h>

#define PLEN 14
#define BATCH 4096
#define N_NODES (BATCH * PLEN)   // 57344
#define BN_EPS 1e-5f

// Output layout: concat of (sim[B], c1[B,800], c2[B,800], e1[B,10], e2[B,10], d1[B,800])
#define O_SIM 0
#define O_C1  4096
#define O_C2  (4096 + 3276800)
#define O_E1  (4096 + 2*3276800)
#define O_E2  (O_E1 + 40960)
#define O_D1  (O_E2 + 40960)

// ---------------- scratch (device globals; no allocation) ----------------
__device__ float g_hA[N_NODES * 128];
__device__ float g_hB[N_NODES * 128];
__device__ float g_h5[(size_t)N_NODES * 1024];
__device__ float g_sum[5][1024];
__device__ float g_sq [5][1024];
__device__ float g_aa [5][1024];
__device__ float g_dd [5][1024];
__device__ float g_e  [2][BATCH * 10];

// ---------------- zero the BN stat accumulators ----------------
__global__ void zero_stats_kernel() {
    int i = blockIdx.x * blockDim.x + threadIdx.x;
    if (i < 5 * 1024) {
        (&g_sum[0][0])[i] = 0.0f;
        (&g_sq [0][0])[i] = 0.0f;
    }
}

// ---------------- layer 1: [N,3] (chain-agg of transposed x) @ W1[3,64] + b1, fused stats ----------------
__global__ void __launch_bounds__(256) layer1_kernel(const float* __restrict__ x,
                                                     const float* __restrict__ W1,
                                                     const float* __restrict__ b1) {
    __shared__ float xg[64][3];
    int tid = threadIdx.x;
    int rowBase = blockIdx.x * 64;
    if (tid < 192) {
        int i = tid / 3, k = tid % 3;
        int n = rowBase + i, b = n / PLEN, p = n % PLEN;
        const float* xb = x + (size_t)b * 3 * PLEN + k * PLEN;
        float v = 0.0f;
        if (p > 0)        v += xb[p - 1];
        if (p < PLEN - 1) v += xb[p + 1];
        xg[i][k] = v;
    }
    __syncthreads();
    int c = tid & 63, rg = tid >> 6;
    float w0 = W1[c], w1 = W1[64 + c], w2 = W1[128 + c], bb = b1[c];
    float s1 = 0.0f, s2 = 0.0f;
    for (int ii = 0; ii < 16; ++ii) {
        int i = rg * 16 + ii;
        float v = fmaf(xg[i][0], w0, fmaf(xg[i][1], w1, fmaf(xg[i][2], w2, bb)));
        g_hA[(size_t)(rowBase + i) * 64 + c] = v;
        s1 += v; s2 = fmaf(v, v, s2);
    }
    atomicAdd(&g_sum[0][c], s1);
    atomicAdd(&g_sq [0][c], s2);
}

// ---------------- BN stats -> affine (a, d): y = a*x + d ----------------
__global__ void bnparams_kernel(int idx, const float* __restrict__ gamma,
                                const float* __restrict__ beta, int C) {
    int c = blockIdx.x * blockDim.x + threadIdx.x;
    if (c >= C) return;
    const float invN = 1.0f / (float)N_NODES;
    float mu  = g_sum[idx][c] * invN;
    float var = g_sq[idx][c] * invN - mu * mu;
    float s = gamma[c] * rsqrtf(var + BN_EPS);
    g_aa[idx][c] = s;
    g_dd[idx][c] = beta[c] - mu * s;
}

// ---------------- generic GCN layer GEMM ----------------
// A-row(n) = relu(a*prev[n-1]+d) + relu(a*prev[n+1]+d) (chain neighbors within molecule)
// out = A @ W + bias, fused per-column sum/sumsq for this layer's BN.
template<int K, int NT>
__global__ void __launch_bounds__(256)
gcn_gemm(const float* __restrict__ W, const float* __restrict__ bias,
         int srcBuf, int dstBuf, int actIdx, int statIdx, int DOUT) {
    constexpr int M = 64, TN = NT / 16, K4 = K / 4, NT4 = NT / 4, MP = M + 4;
    extern __shared__ float sm[];
    float* As = sm;                 // [K][MP]  (k-major, transposed A tile)
    float* Bs = As + K * MP;        // [K][NT]
    float* sA = Bs + K * NT;        // [K]
    float* sD = sA + K;             // [K]

    const float* prev = srcBuf ? g_hB : g_hA;
    float* out = (dstBuf == 2) ? g_h5 : (dstBuf ? g_hB : g_hA);
    const float* av = g_aa[actIdx];
    const float* dv = g_dd[actIdx];

    int tid = threadIdx.x, tx = tid & 15, ty = tid >> 4;
    int rowBase = blockIdx.x * M, colBase = blockIdx.y * NT;

    if (tid < K) { sA[tid] = av[tid]; sD[tid] = dv[tid]; }
    // B tile
    for (int s = tid; s < K * NT4; s += 256) {
        int k = s / NT4, j = (s - k * NT4) * 4;
        float4 w = *reinterpret_cast<const float4*>(W + (size_t)k * DOUT + colBase + j);
        *reinterpret_cast<float4*>(&Bs[k * NT + j]) = w;
    }
    __syncthreads();
    // A tile: aggregated + activated neighbors
    for (int s = tid; s < M * K4; s += 256) {
        int i = s / K4, kq = (s - i * K4) * 4;
        int n = rowBase + i, p = n % PLEN;
        float v0 = 0.f, v1 = 0.f, v2 = 0.f, v3 = 0.f;
        float a0 = sA[kq], a1 = sA[kq + 1], a2 = sA[kq + 2], a3 = sA[kq + 3];
        float d0 = sD[kq], d1 = sD[kq + 1], d2 = sD[kq + 2], d3 = sD[kq + 3];
        if (p > 0) {
            float4 L = *reinterpret_cast<const float4*>(prev + (size_t)(n - 1) * K + kq);
            v0 += fmaxf(fmaf(a0, L.x, d0), 0.f);
            v1 += fmaxf(fmaf(a1, L.y, d1), 0.f);
            v2 += fmaxf(fmaf(a2, L.z, d2), 0.f);
            v3 += fmaxf(fmaf(a3, L.w, d3), 0.f);
        }
        if (p < PLEN - 1) {
            float4 R = *reinterpret_cast<const float4*>(prev + (size_t)(n + 1) * K + kq);
            v0 += fmaxf(fmaf(a0, R.x, d0), 0.f);
            v1 += fmaxf(fmaf(a1, R.y, d1), 0.f);
            v2 += fmaxf(fmaf(a2, R.z, d2), 0.f);
            v3 += fmaxf(fmaf(a3, R.w, d3), 0.f);
        }
        As[(kq + 0) * MP + i] = v0;
        As[(kq + 1) * MP + i] = v1;
        As[(kq + 2) * MP + i] = v2;
        As[(kq + 3) * MP + i] = v3;
    }
    __syncthreads();

    float acc[4][TN];
#pragma unroll
    for (int r = 0; r < 4; ++r)
#pragma unroll
        for (int j = 0; j < TN; ++j) acc[r][j] = 0.0f;

    int r0 = ty * 4, c0 = tx * TN;
#pragma unroll 8
    for (int k = 0; k < K; ++k) {
        float4 a4 = *reinterpret_cast<const float4*>(&As[k * MP + r0]);
        float ar[4] = {a4.x, a4.y, a4.z, a4.w};
        float br[TN];
#pragma unroll
        for (int j = 0; j < TN; j += 4) {
            float4 b4 = *reinterpret_cast<const float4*>(&Bs[k * NT + c0 + j]);
            br[j] = b4.x; br[j + 1] = b4.y; br[j + 2] = b4.z; br[j + 3] = b4.w;
        }
#pragma unroll
        for (int r = 0; r < 4; ++r)
#pragma unroll
            for (int j = 0; j < TN; ++j)
                acc[r][j] = fmaf(ar[r], br[j], acc[r][j]);
    }
    __syncthreads();  // done with As/Bs; reuse As as reduction scratch

    float bl[TN];
#pragma unroll
    for (int j = 0; j < TN; ++j) bl[j] = bias[colBase + c0 + j];

    float s1[TN], s2[TN];
#pragma unroll
    for (int j = 0; j < TN; ++j) { s1[j] = 0.f; s2[j] = 0.f; }

#pragma unroll
    for (int r = 0; r < 4; ++r) {
        float vrow[TN];
#pragma unroll
        for (int j = 0; j < TN; ++j) {
            float v = acc[r][j] + bl[j];
            vrow[j] = v; s1[j] += v; s2[j] = fmaf(v, v, s2[j]);
        }
        float* op = out + (size_t)(rowBase + r0 + r) * DOUT + colBase + c0;
#pragma unroll
        for (int j = 0; j < TN; j += 4) {
            float4 o = make_float4(vrow[j], vrow[j + 1], vrow[j + 2], vrow[j + 3]);
            *reinterpret_cast<float4*>(op + j) = o;
        }
    }
    // block-level column reduction for BN stats
    float* red = As;  // 32*NT floats <= K*MP
#pragma unroll
    for (int j = 0; j < TN; ++j) {
        red[ty * NT + c0 + j] = s1[j];
        red[16 * NT + ty * NT + c0 + j] = s2[j];
    }
    __syncthreads();
    if (tid < NT) {
        float t1 = 0.f, t2 = 0.f;
        for (int y = 0; y < 16; ++y) {
            t1 += red[y * NT + tid];
            t2 += red[16 * NT + y * NT + tid];
        }
        atomicAdd(&g_sum[statIdx][colBase + tid], t1);
        atomicAdd(&g_sq [statIdx][colBase + tid], t2);
    }
}

// ---------------- max-pool over P + embedding (fused) ----------------
__global__ void __launch_bounds__(256)
maxpool_embed_kernel(const float* __restrict__ embW, const float* __restrict__ embB,
                     float* __restrict__ eOut, int fwd) {
    int b = blockIdx.x, tid = threadIdx.x;
    __shared__ float sE[10];
    if (tid < 10) sE[tid] = 0.0f;
    __syncthreads();
    float acc[10];
#pragma unroll
    for (int j = 0; j < 10; ++j) acc[j] = 0.0f;
    const float* base = g_h5 + (size_t)b * PLEN * 1024;
    for (int cc = tid; cc < 1024; cc += 256) {
        float a = g_aa[4][cc], dsh = g_dd[4][cc];
        float m = -3.4e38f;
#pragma unroll
        for (int p = 0; p < PLEN; ++p) {
            float v = base[p * 1024 + cc];
            m = fmaxf(m, fmaf(a, v, dsh));
        }
        float pooled = fmaxf(m, 0.0f);
#pragma unroll
        for (int j = 0; j < 10; ++j)
            acc[j] = fmaf(pooled, embW[cc * 10 + j], acc[j]);
    }
#pragma unroll
    for (int j = 0; j < 10; ++j) {
        float v = acc[j];
        for (int off = 16; off; off >>= 1) v += __shfl_down_sync(0xffffffffu, v, off);
        if ((tid & 31) == 0) atomicAdd(&sE[j], v);
    }
    __syncthreads();
    if (tid < 10) {
        float e = sE[tid] + embB[tid];
        eOut[b * 10 + tid] = e;
        g_e[fwd][b * 10 + tid] = e;
    }
}

// ---------------- cluster assignment: d, q = (1+d)^-1 normalized ----------------
__global__ void __launch_bounds__(256)
cluster_kernel(const float* __restrict__ clu, float* __restrict__ qout,
               float* __restrict__ dout, int fwd) {
    int b = blockIdx.x, tid = threadIdx.x;
    __shared__ float sclu[8000];
    __shared__ float se[10];
    __shared__ float squn[800];
    __shared__ float sred[9];
    for (int s = tid; s < 8000; s += 256) sclu[s] = clu[s];
    if (tid < 10) se[tid] = g_e[fwd][b * 10 + tid];
    __syncthreads();
    float local = 0.0f;
    for (int j = tid; j < 800; j += 256) {
        float dist = 0.0f;
#pragma unroll
        for (int k = 0; k < 10; ++k) {
            float t = se[k] - sclu[j * 10 + k];
            dist = fmaf(t, t, dist);
        }
        float qun = 1.0f / (1.0f + dist);
        squn[j] = qun; local += qun;
        if (dout) dout[(size_t)b * 800 + j] = dist;
    }
    float v = local;
    for (int off = 16; off; off >>= 1) v += __shfl_down_sync(0xffffffffu, v, off);
    if ((tid & 31) == 0) sred[tid >> 5] = v;
    __syncthreads();
    if (tid == 0) {
        float t = 0.f;
        for (int w = 0; w < 8; ++w) t += sred[w];
        sred[8] = 1.0f / t;
    }
    __syncthreads();
    float inv = sred[8];
    for (int j = tid; j < 800; j += 256)
        qout[(size_t)b * 800 + j] = squn[j] * inv;
}

// ---------------- pairwise distance between the two towers ----------------
__global__ void sim_kernel(float* __restrict__ simOut) {
    int i = blockIdx.x * blockDim.x + threadIdx.x;
    if (i >= BATCH) return;
    float s = 0.0f;
#pragma unroll
    for (int k = 0; k < 10; ++k) {
        float t = g_e[0][i * 10 + k] - g_e[1][i * 10 + k] + 1e-6f;
        s = fmaf(t, t, s);
    }
    simOut[i] = sqrtf(s);
}

// ---------------- launch ----------------
extern "C" void kernel_launch(void* const* d_in, const int* in_sizes, int n_in,
                              void* d_out, int out_size) {
    const float* x1 = (const float*)d_in[0];
    const float* x2 = (const float*)d_in[1];
    const float* W[5]; const float* bb[5]; const float* gam[5]; const float* bet[5];
    for (int li = 0; li < 5; ++li) {
        W[li]   = (const float*)d_in[2 + li * 4 + 0];
        bb[li]  = (const float*)d_in[2 + li * 4 + 1];
        gam[li] = (const float*)d_in[2 + li * 4 + 2];
        bet[li] = (const float*)d_in[2 + li * 4 + 3];
    }
    const float* embW = (const float*)d_in[22];
    const float* embB = (const float*)d_in[23];
    const float* clu  = (const float*)d_in[24];
    float* out = (float*)d_out;

    const int SMEM64  = (64 * 68 + 64 * 64 + 2 * 64) * 4;     // 34304 B
    const int SMEM128 = (128 * 68 + 128 * 128 + 2 * 128) * 4; // 101376 B
    cudaFuncSetAttribute((const void*)gcn_gemm<128, 128>,
                         cudaFuncAttributeMaxDynamicSharedMemorySize, SMEM128);

    const int GB = N_NODES / 64;  // 896 row tiles

    for (int f = 0; f < 2; ++f) {
        const float* x = f ? x2 : x1;
        zero_stats_kernel<<<5, 1024>>>();
        layer1_kernel<<<GB, 256>>>(x, W[0], bb[0]);
        bnparams_kernel<<<1, 64>>>(0, gam[0], bet[0], 64);
        gcn_gemm<64, 64><<<dim3(GB, 1), 256, SMEM64>>>(W[1], bb[1], 0, 1, 0, 1, 64);
        bnparams_kernel<<<1, 64>>>(1, gam[1], bet[1], 64);
        gcn_gemm<64, 64><<<dim3(GB, 1), 256, SMEM64>>>(W[2], bb[2], 1, 0, 1, 2, 64);
        bnparams_kernel<<<1, 64>>>(2, gam[2], bet[2], 64);
        gcn_gemm<64, 64><<<dim3(GB, 2), 256, SMEM64>>>(W[3], bb[3], 0, 1, 2, 3, 128);
        bnparams_kernel<<<1, 128>>>(3, gam[3], bet[3], 128);
        gcn_gemm<128, 128><<<dim3(GB, 8), 256, SMEM128>>>(W[4], bb[4], 1, 2, 3, 4, 1024);
        bnparams_kernel<<<4, 256>>>(4, gam[4], bet[4], 1024);
        maxpool_embed_kernel<<<BATCH, 256>>>(embW, embB, out + (f ? O_E2 : O_E1), f);
        cluster_kernel<<<BATCH, 256>>>(clu, out + (f ? O_C2 : O_C1),
                                       f ? (float*)nullptr : out + O_D1, f);
    }
    sim_kernel<<<16, 256>>>(out);
}

// round 5
// speedup vs baseline: 2.2609x; 2.2609x over previous
#include <cuda_runtime.h>
#include <cuda_bf16.h>
#include <math.h>
#include <stdint.h>

#define PLEN 14
#define BATCH 4096
#define N_NODES (BATCH * PLEN)   // 57344
#define BN_EPS 1e-5f

// Output layout: concat of (sim[B], c1[B,800], c2[B,800], e1[B,10], e2[B,10], d1[B,800])
#define O_SIM 0
#define O_C1  4096
#define O_C2  (4096 + 3276800)
#define O_E1  (4096 + 2*3276800)
#define O_E2  (O_E1 + 40960)
#define O_D1  (O_E2 + 40960)

// ---------------- scratch (device globals; no allocation) ----------------
__device__ float g_hA[N_NODES * 128];
__device__ float g_hB[N_NODES * 128];
__device__ float g_h5[(size_t)N_NODES * 1024];
__device__ float g_sum[5][1024];
__device__ float g_sq [5][1024];
__device__ float g_aa [5][1024];
__device__ float g_dd [5][1024];
__device__ float g_e  [2][BATCH * 10];
__device__ __nv_bfloat16 g_A5hi[(size_t)N_NODES * 128];
__device__ __nv_bfloat16 g_A5lo[(size_t)N_NODES * 128];
__device__ __nv_bfloat16 g_W5Th[1024 * 128];   // W5^T hi: [n][k]
__device__ __nv_bfloat16 g_W5Tl[1024 * 128];   // W5^T lo: [n][k]

// ---------------- zero the BN stat accumulators ----------------
__global__ void zero_stats_kernel() {
    int i = blockIdx.x * blockDim.x + threadIdx.x;
    if (i < 5 * 1024) {
        (&g_sum[0][0])[i] = 0.0f;
        (&g_sq [0][0])[i] = 0.0f;
    }
}

// ---------------- layer 1 ----------------
__global__ void __launch_bounds__(256) layer1_kernel(const float* __restrict__ x,
                                                     const float* __restrict__ W1,
                                                     const float* __restrict__ b1) {
    __shared__ float xg[64][3];
    int tid = threadIdx.x;
    int rowBase = blockIdx.x * 64;
    if (tid < 192) {
        int i = tid / 3, k = tid % 3;
        int n = rowBase + i, b = n / PLEN, p = n % PLEN;
        const float* xb = x + (size_t)b * 3 * PLEN + k * PLEN;
        float v = 0.0f;
        if (p > 0)        v += xb[p - 1];
        if (p < PLEN - 1) v += xb[p + 1];
        xg[i][k] = v;
    }
    __syncthreads();
    int c = tid & 63, rg = tid >> 6;
    float w0 = W1[c], w1 = W1[64 + c], w2 = W1[128 + c], bb = b1[c];
    float s1 = 0.0f, s2 = 0.0f;
    for (int ii = 0; ii < 16; ++ii) {
        int i = rg * 16 + ii;
        float v = fmaf(xg[i][0], w0, fmaf(xg[i][1], w1, fmaf(xg[i][2], w2, bb)));
        g_hA[(size_t)(rowBase + i) * 64 + c] = v;
        s1 += v; s2 = fmaf(v, v, s2);
    }
    atomicAdd(&g_sum[0][c], s1);
    atomicAdd(&g_sq [0][c], s2);
}

// ---------------- BN stats -> affine ----------------
__global__ void bnparams_kernel(int idx, const float* __restrict__ gamma,
                                const float* __restrict__ beta, int C) {
    int c = blockIdx.x * blockDim.x + threadIdx.x;
    if (c >= C) return;
    const float invN = 1.0f / (float)N_NODES;
    float mu  = g_sum[idx][c] * invN;
    float var = g_sq[idx][c] * invN - mu * mu;
    float s = gamma[c] * rsqrtf(var + BN_EPS);
    g_aa[idx][c] = s;
    g_dd[idx][c] = beta[c] - mu * s;
}

// ---------------- fp32 GCN GEMM (layers 2-4) ----------------
template<int K, int NT>
__global__ void __launch_bounds__(256)
gcn_gemm(const float* __restrict__ W, const float* __restrict__ bias,
         int srcBuf, int dstBuf, int actIdx, int statIdx, int DOUT) {
    constexpr int M = 64, TN = NT / 16, K4 = K / 4, NT4 = NT / 4, MP = M + 4;
    extern __shared__ float sm[];
    float* As = sm;
    float* Bs = As + K * MP;
    float* sA = Bs + K * NT;
    float* sD = sA + K;

    const float* prev = srcBuf ? g_hB : g_hA;
    float* out = dstBuf ? g_hB : g_hA;
    const float* av = g_aa[actIdx];
    const float* dv = g_dd[actIdx];

    int tid = threadIdx.x, tx = tid & 15, ty = tid >> 4;
    int rowBase = blockIdx.x * M, colBase = blockIdx.y * NT;

    if (tid < K) { sA[tid] = av[tid]; sD[tid] = dv[tid]; }
    for (int s = tid; s < K * NT4; s += 256) {
        int k = s / NT4, j = (s - k * NT4) * 4;
        float4 w = *reinterpret_cast<const float4*>(W + (size_t)k * DOUT + colBase + j);
        *reinterpret_cast<float4*>(&Bs[k * NT + j]) = w;
    }
    __syncthreads();
    for (int s = tid; s < M * K4; s += 256) {
        int i = s / K4, kq = (s - i * K4) * 4;
        int n = rowBase + i, p = n % PLEN;
        float v0 = 0.f, v1 = 0.f, v2 = 0.f, v3 = 0.f;
        float a0 = sA[kq], a1 = sA[kq + 1], a2 = sA[kq + 2], a3 = sA[kq + 3];
        float d0 = sD[kq], d1 = sD[kq + 1], d2 = sD[kq + 2], d3 = sD[kq + 3];
        if (p > 0) {
            float4 L = *reinterpret_cast<const float4*>(prev + (size_t)(n - 1) * K + kq);
            v0 += fmaxf(fmaf(a0, L.x, d0), 0.f);
            v1 += fmaxf(fmaf(a1, L.y, d1), 0.f);
            v2 += fmaxf(fmaf(a2, L.z, d2), 0.f);
            v3 += fmaxf(fmaf(a3, L.w, d3), 0.f);
        }
        if (p < PLEN - 1) {
            float4 R = *reinterpret_cast<const float4*>(prev + (size_t)(n + 1) * K + kq);
            v0 += fmaxf(fmaf(a0, R.x, d0), 0.f);
            v1 += fmaxf(fmaf(a1, R.y, d1), 0.f);
            v2 += fmaxf(fmaf(a2, R.z, d2), 0.f);
            v3 += fmaxf(fmaf(a3, R.w, d3), 0.f);
        }
        As[(kq + 0) * MP + i] = v0;
        As[(kq + 1) * MP + i] = v1;
        As[(kq + 2) * MP + i] = v2;
        As[(kq + 3) * MP + i] = v3;
    }
    __syncthreads();

    float acc[4][TN];
#pragma unroll
    for (int r = 0; r < 4; ++r)
#pragma unroll
        for (int j = 0; j < TN; ++j) acc[r][j] = 0.0f;

    int r0 = ty * 4, c0 = tx * TN;
#pragma unroll 8
    for (int k = 0; k < K; ++k) {
        float4 a4 = *reinterpret_cast<const float4*>(&As[k * MP + r0]);
        float ar[4] = {a4.x, a4.y, a4.z, a4.w};
        float br[TN];
#pragma unroll
        for (int j = 0; j < TN; j += 4) {
            float4 b4 = *reinterpret_cast<const float4*>(&Bs[k * NT + c0 + j]);
            br[j] = b4.x; br[j + 1] = b4.y; br[j + 2] = b4.z; br[j + 3] = b4.w;
        }
#pragma unroll
        for (int r = 0; r < 4; ++r)
#pragma unroll
            for (int j = 0; j < TN; ++j)
                acc[r][j] = fmaf(ar[r], br[j], acc[r][j]);
    }
    __syncthreads();

    float bl[TN];
#pragma unroll
    for (int j = 0; j < TN; ++j) bl[j] = bias[colBase + c0 + j];

    float s1[TN], s2[TN];
#pragma unroll
    for (int j = 0; j < TN; ++j) { s1[j] = 0.f; s2[j] = 0.f; }

#pragma unroll
    for (int r = 0; r < 4; ++r) {
        float vrow[TN];
#pragma unroll
        for (int j = 0; j < TN; ++j) {
            float v = acc[r][j] + bl[j];
            vrow[j] = v; s1[j] += v; s2[j] = fmaf(v, v, s2[j]);
        }
        float* op = out + (size_t)(rowBase + r0 + r) * DOUT + colBase + c0;
#pragma unroll
        for (int j = 0; j < TN; j += 4) {
            float4 o = make_float4(vrow[j], vrow[j + 1], vrow[j + 2], vrow[j + 3]);
            *reinterpret_cast<float4*>(op + j) = o;
        }
    }
    float* red = As;
#pragma unroll
    for (int j = 0; j < TN; ++j) {
        red[ty * NT + c0 + j] = s1[j];
        red[16 * NT + ty * NT + c0 + j] = s2[j];
    }
    __syncthreads();
    if (tid < NT) {
        float t1 = 0.f, t2 = 0.f;
        for (int y = 0; y < 16; ++y) {
            t1 += red[y * NT + tid];
            t2 += red[16 * NT + y * NT + tid];
        }
        atomicAdd(&g_sum[statIdx][colBase + tid], t1);
        atomicAdd(&g_sq [statIdx][colBase + tid], t2);
    }
}

// ================= layer-5 tensor-core path (mma.sync bf16, 3-term split) =================

// W5 fp32 [k][n] -> transposed bf16 hi/lo [n][k]
__global__ void prep_W5_kernel(const float* __restrict__ W5) {
    int i = blockIdx.x * 256 + threadIdx.x;   // 128*1024 total
    int k = i >> 10, n = i & 1023;
    float v = W5[i];
    __nv_bfloat16 h = __float2bfloat16(v);
    g_W5Th[n * 128 + k] = h;
    g_W5Tl[n * 128 + k] = __float2bfloat16(v - __bfloat162float(h));
}

// A' = chain-agg(relu(BN4(g_hB))) -> bf16 hi/lo split, row-major [n][k]
__global__ void __launch_bounds__(256) prep_A5_kernel() {
    int idx = blockIdx.x * 256 + threadIdx.x;     // N_NODES*32
    int n = idx >> 5, kq = (idx & 31) * 4;
    int p = n % PLEN;
    float4 a = *reinterpret_cast<const float4*>(&g_aa[3][kq]);
    float4 d = *reinterpret_cast<const float4*>(&g_dd[3][kq]);
    float v0 = 0.f, v1 = 0.f, v2 = 0.f, v3 = 0.f;
    if (p > 0) {
        float4 L = *reinterpret_cast<const float4*>(g_hB + (size_t)(n - 1) * 128 + kq);
        v0 += fmaxf(fmaf(a.x, L.x, d.x), 0.f);
        v1 += fmaxf(fmaf(a.y, L.y, d.y), 0.f);
        v2 += fmaxf(fmaf(a.z, L.z, d.z), 0.f);
        v3 += fmaxf(fmaf(a.w, L.w, d.w), 0.f);
    }
    if (p < PLEN - 1) {
        float4 R = *reinterpret_cast<const float4*>(g_hB + (size_t)(n + 1) * 128 + kq);
        v0 += fmaxf(fmaf(a.x, R.x, d.x), 0.f);
        v1 += fmaxf(fmaf(a.y, R.y, d.y), 0.f);
        v2 += fmaxf(fmaf(a.z, R.z, d.z), 0.f);
        v3 += fmaxf(fmaf(a.w, R.w, d.w), 0.f);
    }
    __nv_bfloat16 h0 = __float2bfloat16(v0), h1 = __float2bfloat16(v1);
    __nv_bfloat16 h2 = __float2bfloat16(v2), h3 = __float2bfloat16(v3);
    __nv_bfloat16 l0 = __float2bfloat16(v0 - __bfloat162float(h0));
    __nv_bfloat16 l1 = __float2bfloat16(v1 - __bfloat162float(h1));
    __nv_bfloat16 l2 = __float2bfloat16(v2 - __bfloat162float(h2));
    __nv_bfloat16 l3 = __float2bfloat16(v3 - __bfloat162float(h3));
    size_t o = (size_t)n * 128 + kq;
    *reinterpret_cast<__nv_bfloat162*>(g_A5hi + o)     = __nv_bfloat162(h0, h1);
    *reinterpret_cast<__nv_bfloat162*>(g_A5hi + o + 2) = __nv_bfloat162(h2, h3);
    *reinterpret_cast<__nv_bfloat162*>(g_A5lo + o)     = __nv_bfloat162(l0, l1);
    *reinterpret_cast<__nv_bfloat162*>(g_A5lo + o + 2) = __nv_bfloat162(l2, l3);
}

// smem layout (byte offsets); rows padded to 272B (136 bf16) for conflict-free ldmatrix
#define L5_STRIDE 272
#define SM_AHI  0
#define SM_ALO  34816
#define SM_BHI  69632
#define SM_BLO  139264
#define SM_BIAS 208896
#define SM_TOT  209920   // + 1024 bias = 210944

__device__ __forceinline__ uint32_t smem_u32(const void* p) {
    uint32_t a;
    asm("{ .reg .u64 t; cvta.to.shared.u64 t, %1; cvt.u32.u64 %0, t; }" : "=r"(a) : "l"(p));
    return a;
}
__device__ __forceinline__ void ldm4(uint32_t* r, uint32_t addr) {
    asm volatile("ldmatrix.sync.aligned.m8n8.x4.shared.b16 {%0,%1,%2,%3}, [%4];"
                 : "=r"(r[0]), "=r"(r[1]), "=r"(r[2]), "=r"(r[3]) : "r"(addr));
}
__device__ __forceinline__ void mma_bf16(float* c, const uint32_t* a,
                                         uint32_t b0, uint32_t b1) {
    asm volatile(
        "mma.sync.aligned.m16n8k16.row.col.f32.bf16.bf16.f32 "
        "{%0,%1,%2,%3}, {%4,%5,%6,%7}, {%8,%9}, {%0,%1,%2,%3};"
        : "+f"(c[0]), "+f"(c[1]), "+f"(c[2]), "+f"(c[3])
        : "r"(a[0]), "r"(a[1]), "r"(a[2]), "r"(a[3]), "r"(b0), "r"(b1));
}

__global__ void __launch_bounds__(256, 1)
layer5_mma(const float* __restrict__ bias) {
    extern __shared__ char sm5[];
    int tid = threadIdx.x, wid = tid >> 5, lane = tid & 31;
    int rowCta = blockIdx.x * 128, colBase = blockIdx.y * 256;
    float* sbias = reinterpret_cast<float*>(sm5 + SM_BIAS);
    sbias[tid] = bias[colBase + tid];

    // A tiles: 128 rows x 256B data per row (hi and lo)
    {
        const uint4* aH = reinterpret_cast<const uint4*>(g_A5hi) + (size_t)rowCta * 16;
        const uint4* aL = reinterpret_cast<const uint4*>(g_A5lo) + (size_t)rowCta * 16;
#pragma unroll
        for (int t = 0; t < 8; ++t) {
            int s = tid + t * 256;
            int row = s >> 4, c = s & 15;
            *reinterpret_cast<uint4*>(sm5 + SM_AHI + row * L5_STRIDE + c * 16) = aH[s];
            *reinterpret_cast<uint4*>(sm5 + SM_ALO + row * L5_STRIDE + c * 16) = aL[s];
        }
        const uint4* bH = reinterpret_cast<const uint4*>(g_W5Th) + (size_t)colBase * 16;
        const uint4* bL = reinterpret_cast<const uint4*>(g_W5Tl) + (size_t)colBase * 16;
#pragma unroll
        for (int t = 0; t < 16; ++t) {
            int s = tid + t * 256;
            int row = s >> 4, c = s & 15;
            *reinterpret_cast<uint4*>(sm5 + SM_BHI + row * L5_STRIDE + c * 16) = bH[s];
            *reinterpret_cast<uint4*>(sm5 + SM_BLO + row * L5_STRIDE + c * 16) = bL[s];
        }
    }
    __syncthreads();

    int wm = wid >> 2, wn = wid & 3;
    int m0 = wm * 64, n0 = wn * 64;
    int quad = lane >> 3, r8 = lane & 7;
    uint32_t base = smem_u32(sm5);
    // A ldmatrix address: rows m, cols k; quad0: m+0..7,k0; quad1: m+8..15,k0; quad2/3: k0+8
    uint32_t aBase = base + SM_AHI + (uint32_t)((m0 + (quad & 1) * 8 + r8) * L5_STRIDE + (quad >> 1) * 16);
    // B ldmatrix address: rows n, cols k; quad0: n+0..7,k0; quad1: n+0..7,k0+8; quad2/3: n+8..15
    uint32_t bBase = base + SM_BHI + (uint32_t)((n0 + (quad >> 1) * 8 + r8) * L5_STRIDE + (quad & 1) * 16);

    float acc[4][8][4];
#pragma unroll
    for (int mi = 0; mi < 4; ++mi)
#pragma unroll
        for (int nf = 0; nf < 8; ++nf)
#pragma unroll
            for (int j = 0; j < 4; ++j) acc[mi][nf][j] = 0.0f;

#pragma unroll 1
    for (int term = 0; term < 3; ++term) {
        uint32_t aB = aBase + (term == 2 ? (SM_ALO - SM_AHI) : 0u);
        uint32_t bB = bBase + (term == 1 ? (SM_BLO - SM_BHI) : 0u);
#pragma unroll
        for (int ks = 0; ks < 8; ++ks) {
            uint32_t a[4][4], b[4][4];
#pragma unroll
            for (int mi = 0; mi < 4; ++mi)
                ldm4(a[mi], aB + mi * 16 * L5_STRIDE + ks * 32);
#pragma unroll
            for (int nj = 0; nj < 4; ++nj)
                ldm4(b[nj], bB + nj * 16 * L5_STRIDE + ks * 32);
#pragma unroll
            for (int mi = 0; mi < 4; ++mi)
#pragma unroll
                for (int nf = 0; nf < 8; ++nf)
                    mma_bf16(acc[mi][nf], a[mi],
                             b[nf >> 1][(nf & 1) * 2], b[nf >> 1][(nf & 1) * 2 + 1]);
        }
    }

    // epilogue: bias, store pre-BN h5, fused column stats
    float bl[8][2];
#pragma unroll
    for (int nf = 0; nf < 8; ++nf) {
        bl[nf][0] = sbias[n0 + nf * 8 + (lane & 3) * 2];
        bl[nf][1] = sbias[n0 + nf * 8 + (lane & 3) * 2 + 1];
    }
    float s1[8][2], s2[8][2];
#pragma unroll
    for (int nf = 0; nf < 8; ++nf) { s1[nf][0] = s1[nf][1] = 0.f; s2[nf][0] = s2[nf][1] = 0.f; }

#pragma unroll
    for (int mi = 0; mi < 4; ++mi) {
        int rLo = rowCta + m0 + mi * 16 + (lane >> 2);
        float* pLo = g_h5 + (size_t)rLo * 1024 + colBase + n0 + (lane & 3) * 2;
        float* pHi = pLo + 8 * 1024;
#pragma unroll
        for (int nf = 0; nf < 8; ++nf) {
            float c0 = acc[mi][nf][0] + bl[nf][0];
            float c1 = acc[mi][nf][1] + bl[nf][1];
            float c2 = acc[mi][nf][2] + bl[nf][0];
            float c3 = acc[mi][nf][3] + bl[nf][1];
            *reinterpret_cast<float2*>(pLo + nf * 8) = make_float2(c0, c1);
            *reinterpret_cast<float2*>(pHi + nf * 8) = make_float2(c2, c3);
            s1[nf][0] += c0 + c2;           s1[nf][1] += c1 + c3;
            s2[nf][0] += c0 * c0 + c2 * c2; s2[nf][1] += c1 * c1 + c3 * c3;
        }
    }
#pragma unroll
    for (int nf = 0; nf < 8; ++nf)
#pragma unroll
        for (int j = 0; j < 2; ++j) {
            float v1 = s1[nf][j], v2 = s2[nf][j];
            v1 += __shfl_xor_sync(0xffffffffu, v1, 4);
            v1 += __shfl_xor_sync(0xffffffffu, v1, 8);
            v1 += __shfl_xor_sync(0xffffffffu, v1, 16);
            v2 += __shfl_xor_sync(0xffffffffu, v2, 4);
            v2 += __shfl_xor_sync(0xffffffffu, v2, 8);
            v2 += __shfl_xor_sync(0xffffffffu, v2, 16);
            if (lane < 4) {
                int col = colBase + n0 + nf * 8 + lane * 2 + j;
                atomicAdd(&g_sum[4][col], v1);
                atomicAdd(&g_sq [4][col], v2);
            }
        }
}

// ---------------- max-pool over P + embedding (fused) ----------------
__global__ void __launch_bounds__(256)
maxpool_embed_kernel(const float* __restrict__ embW, const float* __restrict__ embB,
                     float* __restrict__ eOut, int fwd) {
    int b = blockIdx.x, tid = threadIdx.x;
    __shared__ float sE[10];
    if (tid < 10) sE[tid] = 0.0f;
    __syncthreads();
    float acc[10];
#pragma unroll
    for (int j = 0; j < 10; ++j) acc[j] = 0.0f;
    const float* base = g_h5 + (size_t)b * PLEN * 1024;
    for (int cc = tid; cc < 1024; cc += 256) {
        float a = g_aa[4][cc], dsh = g_dd[4][cc];
        float m = -3.4e38f;
#pragma unroll
        for (int p = 0; p < PLEN; ++p) {
            float v = base[p * 1024 + cc];
            m = fmaxf(m, fmaf(a, v, dsh));
        }
        float pooled = fmaxf(m, 0.0f);
#pragma unroll
        for (int j = 0; j < 10; ++j)
            acc[j] = fmaf(pooled, embW[cc * 10 + j], acc[j]);
    }
#pragma unroll
    for (int j = 0; j < 10; ++j) {
        float v = acc[j];
        for (int off = 16; off; off >>= 1) v += __shfl_down_sync(0xffffffffu, v, off);
        if ((tid & 31) == 0) atomicAdd(&sE[j], v);
    }
    __syncthreads();
    if (tid < 10) {
        float e = sE[tid] + embB[tid];
        eOut[b * 10 + tid] = e;
        g_e[fwd][b * 10 + tid] = e;
    }
}

// ---------------- cluster assignment ----------------
__global__ void __launch_bounds__(256)
cluster_kernel(const float* __restrict__ clu, float* __restrict__ qout,
               float* __restrict__ dout, int fwd) {
    int b = blockIdx.x, tid = threadIdx.x;
    __shared__ float sclu[8000];
    __shared__ float se[10];
    __shared__ float squn[800];
    __shared__ float sred[9];
    for (int s = tid; s < 8000; s += 256) sclu[s] = clu[s];
    if (tid < 10) se[tid] = g_e[fwd][b * 10 + tid];
    __syncthreads();
    float local = 0.0f;
    for (int j = tid; j < 800; j += 256) {
        float dist = 0.0f;
#pragma unroll
        for (int k = 0; k < 10; ++k) {
            float t = se[k] - sclu[j * 10 + k];
            dist = fmaf(t, t, dist);
        }
        float qun = 1.0f / (1.0f + dist);
        squn[j] = qun; local += qun;
        if (dout) dout[(size_t)b * 800 + j] = dist;
    }
    float v = local;
    for (int off = 16; off; off >>= 1) v += __shfl_down_sync(0xffffffffu, v, off);
    if ((tid & 31) == 0) sred[tid >> 5] = v;
    __syncthreads();
    if (tid == 0) {
        float t = 0.f;
        for (int w = 0; w < 8; ++w) t += sred[w];
        sred[8] = 1.0f / t;
    }
    __syncthreads();
    float inv = sred[8];
    for (int j = tid; j < 800; j += 256)
        qout[(size_t)b * 800 + j] = squn[j] * inv;
}

// ---------------- pairwise distance ----------------
__global__ void sim_kernel(float* __restrict__ simOut) {
    int i = blockIdx.x * blockDim.x + threadIdx.x;
    if (i >= BATCH) return;
    float s = 0.0f;
#pragma unroll
    for (int k = 0; k < 10; ++k) {
        float t = g_e[0][i * 10 + k] - g_e[1][i * 10 + k] + 1e-6f;
        s = fmaf(t, t, s);
    }
    simOut[i] = sqrtf(s);
}

// ---------------- launch ----------------
extern "C" void kernel_launch(void* const* d_in, const int* in_sizes, int n_in,
                              void* d_out, int out_size) {
    const float* x1 = (const float*)d_in[0];
    const float* x2 = (const float*)d_in[1];
    const float* W[5]; const float* bb[5]; const float* gam[5]; const float* bet[5];
    for (int li = 0; li < 5; ++li) {
        W[li]   = (const float*)d_in[2 + li * 4 + 0];
        bb[li]  = (const float*)d_in[2 + li * 4 + 1];
        gam[li] = (const float*)d_in[2 + li * 4 + 2];
        bet[li] = (const float*)d_in[2 + li * 4 + 3];
    }
    const float* embW = (const float*)d_in[22];
    const float* embB = (const float*)d_in[23];
    const float* clu  = (const float*)d_in[24];
    float* out = (float*)d_out;

    const int SMEM64 = (64 * 68 + 64 * 64 + 2 * 64) * 4;
    const int SM5 = SM_TOT + 1024;
    cudaFuncSetAttribute((const void*)layer5_mma,
                         cudaFuncAttributeMaxDynamicSharedMemorySize, SM5);

    const int GB = N_NODES / 64;  // 896

    prep_W5_kernel<<<512, 256>>>(W[4]);

    for (int f = 0; f < 2; ++f) {
        const float* x = f ? x2 : x1;
        zero_stats_kernel<<<5, 1024>>>();
        layer1_kernel<<<GB, 256>>>(x, W[0], bb[0]);
        bnparams_kernel<<<1, 64>>>(0, gam[0], bet[0], 64);
        gcn_gemm<64, 64><<<dim3(GB, 1), 256, SMEM64>>>(W[1], bb[1], 0, 1, 0, 1, 64);
        bnparams_kernel<<<1, 64>>>(1, gam[1], bet[1], 64);
        gcn_gemm<64, 64><<<dim3(GB, 1), 256, SMEM64>>>(W[2], bb[2], 1, 0, 1, 2, 64);
        bnparams_kernel<<<1, 64>>>(2, gam[2], bet[2], 64);
        gcn_gemm<64, 64><<<dim3(GB, 2), 256, SMEM64>>>(W[3], bb[3], 0, 1, 2, 3, 128);
        bnparams_kernel<<<1, 128>>>(3, gam[3], bet[3], 128);
        prep_A5_kernel<<<N_NODES * 32 / 256, 256>>>();
        layer5_mma<<<dim3(448, 4), 256, SM5>>>(bb[4]);
        bnparams_kernel<<<4, 256>>>(4, gam[4], bet[4], 1024);
        maxpool_embed_kernel<<<BATCH, 256>>>(embW, embB, out + (f ? O_E2 : O_E1), f);
        cluster_kernel<<<BATCH, 256>>>(clu, out + (f ? O_C2 : O_C1),
                                       f ? (float*)nullptr : out + O_D1, f);
    }
    sim_kernel<<<16, 256>>>(out);
}

// round 9
// speedup vs baseline: 2.4872x; 1.1001x over previous
#include <cuda_runtime.h>
#include <cuda_bf16.h>
#include <math.h>
#include <stdint.h>
#include <float.h>

#define PLEN 14
#define BATCH 4096
#define N_NODES (BATCH * PLEN)   // 57344
#define BN_EPS 1e-5f

// Output layout: concat of (sim[B], c1[B,800], c2[B,800], e1[B,10], e2[B,10], d1[B,800])
#define O_SIM 0
#define O_C1  4096
#define O_C2  (4096 + 3276800)
#define O_E1  (4096 + 2*3276800)
#define O_E2  (O_E1 + 40960)
#define O_D1  (O_E2 + 40960)

// ---------------- scratch (device globals; no allocation) ----------------
__device__ float g_hA[N_NODES * 128];
__device__ float g_hB[N_NODES * 128];
__device__ float g_sum[5][1024];
__device__ float g_sq [5][1024];
__device__ float g_aa5[1024];
__device__ float g_dd5[1024];
__device__ float g_e  [2][BATCH * 10];
__device__ __nv_bfloat16 g_A5hi[(size_t)N_NODES * 128];
__device__ __nv_bfloat16 g_A5lo[(size_t)N_NODES * 128];
__device__ __nv_bfloat16 g_W5Th[1024 * 128];   // W5^T hi: [n][k]
__device__ __nv_bfloat16 g_W5Tl[1024 * 128];   // W5^T lo: [n][k]
// per-(molecule,col) pooling partials: head (start-CTA) and tail (end-CTA, split only)
__device__ float g_mxH[BATCH * 1024], g_mnH[BATCH * 1024];
__device__ float g_mxT[BATCH * 1024], g_mnT[BATCH * 1024];

// ---------------- zero the BN stat accumulators ----------------
__global__ void zero_stats_kernel() {
    int i = blockIdx.x * blockDim.x + threadIdx.x;
    if (i < 5 * 1024) {
        (&g_sum[0][0])[i] = 0.0f;
        (&g_sq [0][0])[i] = 0.0f;
    }
}

// ---------------- W5 fp32 [k][n] -> transposed bf16 hi/lo [n][k] (once) ----------------
__global__ void prep_W5_kernel(const float* __restrict__ W5) {
    int i = blockIdx.x * 256 + threadIdx.x;   // 128*1024 total
    int k = i >> 10, n = i & 1023;
    float v = W5[i];
    __nv_bfloat16 h = __float2bfloat16(v);
    g_W5Th[n * 128 + k] = h;
    g_W5Tl[n * 128 + k] = __float2bfloat16(v - __bfloat162float(h));
}

// ---------------- layer 1 ----------------
__global__ void __launch_bounds__(256) layer1_kernel(const float* __restrict__ x,
                                                     const float* __restrict__ W1,
                                                     const float* __restrict__ b1) {
    __shared__ float xg[64][3];
    int tid = threadIdx.x;
    int rowBase = blockIdx.x * 64;
    if (tid < 192) {
        int i = tid / 3, k = tid % 3;
        int n = rowBase + i, b = n / PLEN, p = n % PLEN;
        const float* xb = x + (size_t)b * 3 * PLEN + k * PLEN;
        float v = 0.0f;
        if (p > 0)        v += xb[p - 1];
        if (p < PLEN - 1) v += xb[p + 1];
        xg[i][k] = v;
    }
    __syncthreads();
    int c = tid & 63, rg = tid >> 6;
    float w0 = W1[c], w1 = W1[64 + c], w2 = W1[128 + c], bb = b1[c];
    float s1 = 0.0f, s2 = 0.0f;
    for (int ii = 0; ii < 16; ++ii) {
        int i = rg * 16 + ii;
        float v = fmaf(xg[i][0], w0, fmaf(xg[i][1], w1, fmaf(xg[i][2], w2, bb)));
        g_hA[(size_t)(rowBase + i) * 64 + c] = v;
        s1 += v; s2 = fmaf(v, v, s2);
    }
    atomicAdd(&g_sum[0][c], s1);
    atomicAdd(&g_sq [0][c], s2);
}

// ---------------- BN stats -> affine (layer-5 stats only) ----------------
__global__ void bnparams_kernel(const float* __restrict__ gamma,
                                const float* __restrict__ beta) {
    int c = blockIdx.x * blockDim.x + threadIdx.x;
    const float invN = 1.0f / (float)N_NODES;
    float mu  = g_sum[4][c] * invN;
    float var = g_sq[4][c] * invN - mu * mu;
    float s = gamma[c] * rsqrtf(var + BN_EPS);
    g_aa5[c] = s;
    g_dd5[c] = beta[c] - mu * s;
}

// ---------------- fp32 GCN GEMM (layers 2-4), in-block BN affine ----------------
template<int K, int NT>
__global__ void __launch_bounds__(256)
gcn_gemm(const float* __restrict__ W, const float* __restrict__ bias,
         int srcBuf, int dstBuf,
         const float* __restrict__ gammaP, const float* __restrict__ betaP,
         int statPrev, int statIdx, int DOUT) {
    constexpr int M = 64, TN = NT / 16, K4 = K / 4, NT4 = NT / 4, MP = M + 4;
    extern __shared__ float sm[];
    float* As = sm;
    float* Bs = As + K * MP;
    float* sA = Bs + K * NT;
    float* sD = sA + K;

    const float* prev = srcBuf ? g_hB : g_hA;
    float* out = dstBuf ? g_hB : g_hA;

    int tid = threadIdx.x, tx = tid & 15, ty = tid >> 4;
    int rowBase = blockIdx.x * M, colBase = blockIdx.y * NT;

    if (tid < K) {
        const float invN = 1.0f / (float)N_NODES;
        float mu  = g_sum[statPrev][tid] * invN;
        float var = g_sq[statPrev][tid] * invN - mu * mu;
        float s = gammaP[tid] * rsqrtf(var + BN_EPS);
        sA[tid] = s; sD[tid] = betaP[tid] - mu * s;
    }
    for (int s = tid; s < K * NT4; s += 256) {
        int k = s / NT4, j = (s - k * NT4) * 4;
        float4 w = *reinterpret_cast<const float4*>(W + (size_t)k * DOUT + colBase + j);
        *reinterpret_cast<float4*>(&Bs[k * NT + j]) = w;
    }
    __syncthreads();
    for (int s = tid; s < M * K4; s += 256) {
        int i = s / K4, kq = (s - i * K4) * 4;
        int n = rowBase + i, p = n % PLEN;
        float v0 = 0.f, v1 = 0.f, v2 = 0.f, v3 = 0.f;
        float a0 = sA[kq], a1 = sA[kq + 1], a2 = sA[kq + 2], a3 = sA[kq + 3];
        float d0 = sD[kq], d1 = sD[kq + 1], d2 = sD[kq + 2], d3 = sD[kq + 3];
        if (p > 0) {
            float4 L = *reinterpret_cast<const float4*>(prev + (size_t)(n - 1) * K + kq);
            v0 += fmaxf(fmaf(a0, L.x, d0), 0.f);
            v1 += fmaxf(fmaf(a1, L.y, d1), 0.f);
            v2 += fmaxf(fmaf(a2, L.z, d2), 0.f);
            v3 += fmaxf(fmaf(a3, L.w, d3), 0.f);
        }
        if (p < PLEN - 1) {
            float4 R = *reinterpret_cast<const float4*>(prev + (size_t)(n + 1) * K + kq);
            v0 += fmaxf(fmaf(a0, R.x, d0), 0.f);
            v1 += fmaxf(fmaf(a1, R.y, d1), 0.f);
            v2 += fmaxf(fmaf(a2, R.z, d2), 0.f);
            v3 += fmaxf(fmaf(a3, R.w, d3), 0.f);
        }
        As[(kq + 0) * MP + i] = v0;
        As[(kq + 1) * MP + i] = v1;
        As[(kq + 2) * MP + i] = v2;
        As[(kq + 3) * MP + i] = v3;
    }
    __syncthreads();

    float acc[4][TN];
#pragma unroll
    for (int r = 0; r < 4; ++r)
#pragma unroll
        for (int j = 0; j < TN; ++j) acc[r][j] = 0.0f;

    int r0 = ty * 4, c0 = tx * TN;
#pragma unroll 8
    for (int k = 0; k < K; ++k) {
        float4 a4 = *reinterpret_cast<const float4*>(&As[k * MP + r0]);
        float ar[4] = {a4.x, a4.y, a4.z, a4.w};
        float br[TN];
#pragma unroll
        for (int j = 0; j < TN; j += 4) {
            float4 b4 = *reinterpret_cast<const float4*>(&Bs[k * NT + c0 + j]);
            br[j] = b4.x; br[j + 1] = b4.y; br[j + 2] = b4.z; br[j + 3] = b4.w;
        }
#pragma unroll
        for (int r = 0; r < 4; ++r)
#pragma unroll
            for (int j = 0; j < TN; ++j)
                acc[r][j] = fmaf(ar[r], br[j], acc[r][j]);
    }
    __syncthreads();

    float bl[TN];
#pragma unroll
    for (int j = 0; j < TN; ++j) bl[j] = bias[colBase + c0 + j];

    float s1[TN], s2[TN];
#pragma unroll
    for (int j = 0; j < TN; ++j) { s1[j] = 0.f; s2[j] = 0.f; }

#pragma unroll
    for (int r = 0; r < 4; ++r) {
        float vrow[TN];
#pragma unroll
        for (int j = 0; j < TN; ++j) {
            float v = acc[r][j] + bl[j];
            vrow[j] = v; s1[j] += v; s2[j] = fmaf(v, v, s2[j]);
        }
        float* op = out + (size_t)(rowBase + r0 + r) * DOUT + colBase + c0;
#pragma unroll
        for (int j = 0; j < TN; j += 4) {
            float4 o = make_float4(vrow[j], vrow[j + 1], vrow[j + 2], vrow[j + 3]);
            *reinterpret_cast<float4*>(op + j) = o;
        }
    }
    float* red = As;
#pragma unroll
    for (int j = 0; j < TN; ++j) {
        red[ty * NT + c0 + j] = s1[j];
        red[16 * NT + ty * NT + c0 + j] = s2[j];
    }
    __syncthreads();
    if (tid < NT) {
        float t1 = 0.f, t2 = 0.f;
        for (int y = 0; y < 16; ++y) {
            t1 += red[y * NT + tid];
            t2 += red[16 * NT + y * NT + tid];
        }
        atomicAdd(&g_sum[statIdx][colBase + tid], t1);
        atomicAdd(&g_sq [statIdx][colBase + tid], t2);
    }
}

// ================= layer-5 tensor-core path =================

// A' = chain-agg(relu(BN4(g_hB))) -> bf16 hi/lo, affine computed per-block
__global__ void __launch_bounds__(256) prep_A5_kernel(const float* __restrict__ gamma,
                                                      const float* __restrict__ beta) {
    __shared__ float sa[128], sd[128];
    int tid = threadIdx.x;
    if (tid < 128) {
        const float invN = 1.0f / (float)N_NODES;
        float mu  = g_sum[3][tid] * invN;
        float var = g_sq[3][tid] * invN - mu * mu;
        float s = gamma[tid] * rsqrtf(var + BN_EPS);
        sa[tid] = s; sd[tid] = beta[tid] - mu * s;
    }
    __syncthreads();
    int rowCta = blockIdx.x * 128;
    for (int u = tid; u < 128 * 32; u += 256) {
        int i = u >> 5, kq = (u & 31) * 4;
        int n = rowCta + i, p = n % PLEN;
        float4 a = *reinterpret_cast<const float4*>(sa + kq);
        float4 d = *reinterpret_cast<const float4*>(sd + kq);
        float v0 = 0.f, v1 = 0.f, v2 = 0.f, v3 = 0.f;
        if (p > 0) {
            float4 L = *reinterpret_cast<const float4*>(g_hB + (size_t)(n - 1) * 128 + kq);
            v0 += fmaxf(fmaf(a.x, L.x, d.x), 0.f);
            v1 += fmaxf(fmaf(a.y, L.y, d.y), 0.f);
            v2 += fmaxf(fmaf(a.z, L.z, d.z), 0.f);
            v3 += fmaxf(fmaf(a.w, L.w, d.w), 0.f);
        }
        if (p < PLEN - 1) {
            float4 R = *reinterpret_cast<const float4*>(g_hB + (size_t)(n + 1) * 128 + kq);
            v0 += fmaxf(fmaf(a.x, R.x, d.x), 0.f);
            v1 += fmaxf(fmaf(a.y, R.y, d.y), 0.f);
            v2 += fmaxf(fmaf(a.z, R.z, d.z), 0.f);
            v3 += fmaxf(fmaf(a.w, R.w, d.w), 0.f);
        }
        __nv_bfloat16 h0 = __float2bfloat16(v0), h1 = __float2bfloat16(v1);
        __nv_bfloat16 h2 = __float2bfloat16(v2), h3 = __float2bfloat16(v3);
        __nv_bfloat16 l0 = __float2bfloat16(v0 - __bfloat162float(h0));
        __nv_bfloat16 l1 = __float2bfloat16(v1 - __bfloat162float(h1));
        __nv_bfloat16 l2 = __float2bfloat16(v2 - __bfloat162float(h2));
        __nv_bfloat16 l3 = __float2bfloat16(v3 - __bfloat162float(h3));
        size_t o = (size_t)n * 128 + kq;
        *reinterpret_cast<__nv_bfloat162*>(g_A5hi + o)     = __nv_bfloat162(h0, h1);
        *reinterpret_cast<__nv_bfloat162*>(g_A5hi + o + 2) = __nv_bfloat162(h2, h3);
        *reinterpret_cast<__nv_bfloat162*>(g_A5lo + o)     = __nv_bfloat162(l0, l1);
        *reinterpret_cast<__nv_bfloat162*>(g_A5lo + o + 2) = __nv_bfloat162(l2, l3);
    }
}

// smem layout (byte offsets); rows padded to 272B for conflict-free ldmatrix
#define L5_STRIDE 272
#define SM_AHI  0
#define SM_ALO  34816
#define SM_BHI  69632
#define SM_BLO  139264
#define SM_BIAS 208896
#define SM_TOT  209920

__device__ __forceinline__ uint32_t smem_u32(const void* p) {
    uint32_t a;
    asm("{ .reg .u64 t; cvta.to.shared.u64 t, %1; cvt.u32.u64 %0, t; }" : "=r"(a) : "l"(p));
    return a;
}
__device__ __forceinline__ void ldm4(uint32_t* r, uint32_t addr) {
    asm volatile("ldmatrix.sync.aligned.m8n8.x4.shared.b16 {%0,%1,%2,%3}, [%4];"
                 : "=r"(r[0]), "=r"(r[1]), "=r"(r[2]), "=r"(r[3]) : "r"(addr));
}
__device__ __forceinline__ void mma_bf16(float* c, const uint32_t* a,
                                         uint32_t b0, uint32_t b1) {
    asm volatile(
        "mma.sync.aligned.m16n8k16.row.col.f32.bf16.bf16.f32 "
        "{%0,%1,%2,%3}, {%4,%5,%6,%7}, {%8,%9}, {%0,%1,%2,%3};"
        : "+f"(c[0]), "+f"(c[1]), "+f"(c[2]), "+f"(c[3])
        : "r"(a[0]), "r"(a[1]), "r"(a[2]), "r"(a[3]), "r"(b0), "r"(b1));
}

__global__ void __launch_bounds__(256, 1)
layer5_mma(const float* __restrict__ bias) {
    extern __shared__ char sm5[];
    int tid = threadIdx.x, wid = tid >> 5, lane = tid & 31;
    int rowCta = blockIdx.x * 128, colBase = blockIdx.y * 256;
    float* sbias = reinterpret_cast<float*>(sm5 + SM_BIAS);
    sbias[tid] = bias[colBase + tid];

    {
        const uint4* aH = reinterpret_cast<const uint4*>(g_A5hi) + (size_t)rowCta * 16;
        const uint4* aL = reinterpret_cast<const uint4*>(g_A5lo) + (size_t)rowCta * 16;
#pragma unroll
        for (int t = 0; t < 8; ++t) {
            int s = tid + t * 256;
            int row = s >> 4, c = s & 15;
            *reinterpret_cast<uint4*>(sm5 + SM_AHI + row * L5_STRIDE + c * 16) = aH[s];
            *reinterpret_cast<uint4*>(sm5 + SM_ALO + row * L5_STRIDE + c * 16) = aL[s];
        }
        const uint4* bH = reinterpret_cast<const uint4*>(g_W5Th) + (size_t)colBase * 16;
        const uint4* bL = reinterpret_cast<const uint4*>(g_W5Tl) + (size_t)colBase * 16;
#pragma unroll
        for (int t = 0; t < 16; ++t) {
            int s = tid + t * 256;
            int row = s >> 4, c = s & 15;
            *reinterpret_cast<uint4*>(sm5 + SM_BHI + row * L5_STRIDE + c * 16) = bH[s];
            *reinterpret_cast<uint4*>(sm5 + SM_BLO + row * L5_STRIDE + c * 16) = bL[s];
        }
    }
    __syncthreads();

    int wm = wid >> 2, wn = wid & 3;
    int m0 = wm * 64, n0 = wn * 64;
    int quad = lane >> 3, r8 = lane & 7;
    uint32_t base = smem_u32(sm5);
    uint32_t aBase = base + SM_AHI + (uint32_t)((m0 + (quad & 1) * 8 + r8) * L5_STRIDE + (quad >> 1) * 16);
    uint32_t bBase = base + SM_BHI + (uint32_t)((n0 + (quad >> 1) * 8 + r8) * L5_STRIDE + (quad & 1) * 16);

    float acc[4][8][4];
#pragma unroll
    for (int mi = 0; mi < 4; ++mi)
#pragma unroll
        for (int nf = 0; nf < 8; ++nf)
#pragma unroll
            for (int j = 0; j < 4; ++j) acc[mi][nf][j] = 0.0f;

#pragma unroll 1
    for (int term = 0; term < 3; ++term) {
        uint32_t aB = aBase + (term == 2 ? (SM_ALO - SM_AHI) : 0u);
        uint32_t bB = bBase + (term == 1 ? (SM_BLO - SM_BHI) : 0u);
#pragma unroll
        for (int ks = 0; ks < 8; ++ks) {
            uint32_t a[4][4], b[4][4];
#pragma unroll
            for (int mi = 0; mi < 4; ++mi)
                ldm4(a[mi], aB + mi * 16 * L5_STRIDE + ks * 32);
#pragma unroll
            for (int nj = 0; nj < 4; ++nj)
                ldm4(b[nj], bBase == 0 ? 0 : bB + nj * 16 * L5_STRIDE + ks * 32);
#pragma unroll
            for (int mi = 0; mi < 4; ++mi)
#pragma unroll
                for (int nf = 0; nf < 8; ++nf)
                    mma_bf16(acc[mi][nf], a[mi],
                             b[nf >> 1][(nf & 1) * 2], b[nf >> 1][(nf & 1) * 2 + 1]);
        }
    }

    // stage tile in smem (reuse A/B area), fused stats
    __syncthreads();   // all warps done with ldmatrix before overwrite
    float* stag = reinterpret_cast<float*>(sm5);   // [128][260] floats
    float s1[8][2], s2[8][2];
#pragma unroll
    for (int nf = 0; nf < 8; ++nf) { s1[nf][0] = s1[nf][1] = 0.f; s2[nf][0] = s2[nf][1] = 0.f; }

#pragma unroll
    for (int mi = 0; mi < 4; ++mi) {
        int rl = m0 + mi * 16 + (lane >> 2);
#pragma unroll
        for (int nf = 0; nf < 8; ++nf) {
            int cl = n0 + nf * 8 + (lane & 3) * 2;
            float b0 = sbias[cl], b1 = sbias[cl + 1];
            float c0 = acc[mi][nf][0] + b0, c1 = acc[mi][nf][1] + b1;
            float c2 = acc[mi][nf][2] + b0, c3 = acc[mi][nf][3] + b1;
            stag[rl * 260 + cl] = c0;       stag[rl * 260 + cl + 1] = c1;
            stag[(rl + 8) * 260 + cl] = c2; stag[(rl + 8) * 260 + cl + 1] = c3;
            s1[nf][0] += c0 + c2;           s1[nf][1] += c1 + c3;
            s2[nf][0] += c0 * c0 + c2 * c2; s2[nf][1] += c1 * c1 + c3 * c3;
        }
    }
#pragma unroll
    for (int nf = 0; nf < 8; ++nf)
#pragma unroll
        for (int j = 0; j < 2; ++j) {
            float v1 = s1[nf][j], v2 = s2[nf][j];
            v1 += __shfl_xor_sync(0xffffffffu, v1, 4);
            v1 += __shfl_xor_sync(0xffffffffu, v1, 8);
            v1 += __shfl_xor_sync(0xffffffffu, v1, 16);
            v2 += __shfl_xor_sync(0xffffffffu, v2, 4);
            v2 += __shfl_xor_sync(0xffffffffu, v2, 8);
            v2 += __shfl_xor_sync(0xffffffffu, v2, 16);
            if (lane < 4) {
                int col = colBase + n0 + nf * 8 + lane * 2 + j;
                atomicAdd(&g_sum[4][col], v1);
                atomicAdd(&g_sq [4][col], v2);
            }
        }
    __syncthreads();

    // per-molecule max/min scan -> head/tail buffers (no atomics)
    int bStart = rowCta / PLEN, bEnd = (rowCta + 127) / PLEN;
    int nm = bEnd - bStart + 1;
    for (int tk = tid; tk < nm * 256; tk += 256) {
        int bi = tk >> 8, c = tk & 255;
        int b = bStart + bi;
        int r0 = b * PLEN - rowCta, r1 = r0 + PLEN;
        int a0 = r0 > 0 ? r0 : 0, a1 = r1 < 128 ? r1 : 128;
        float mx = -FLT_MAX, mn = FLT_MAX;
        for (int r = a0; r < a1; ++r) {
            float v = stag[r * 260 + c];
            mx = fmaxf(mx, v); mn = fminf(mn, v);
        }
        size_t gi = (size_t)b * 1024 + colBase + c;
        if (r0 >= 0) { g_mxH[gi] = mx; g_mnH[gi] = mn; }
        else         { g_mxT[gi] = mx; g_mnT[gi] = mn; }
    }
}

// ---------------- max-pool (from head/tail partials) + embedding ----------------
__global__ void __launch_bounds__(256)
maxpool_embed_kernel(const float* __restrict__ embW, const float* __restrict__ embB,
                     float* __restrict__ eOut, int fwd) {
    int b = blockIdx.x, tid = threadIdx.x;
    int sCta = (b * PLEN) / 128, eCta = (b * PLEN + PLEN - 1) / 128;
    bool split = sCta != eCta;
    __shared__ float sE[10];
    if (tid < 10) sE[tid] = 0.0f;
    __syncthreads();
    float acc[10];
#pragma unroll
    for (int j = 0; j < 10; ++j) acc[j] = 0.0f;
    for (int cc = tid; cc < 1024; cc += 256) {
        size_t gi = (size_t)b * 1024 + cc;
        float mx = g_mxH[gi], mn = g_mnH[gi];
        if (split) {
            mx = fmaxf(mx, g_mxT[gi]);
            mn = fminf(mn, g_mnT[gi]);
        }
        float a = g_aa5[cc], d = g_dd5[cc];
        float pooled = fmaxf(fmaxf(fmaf(a, mx, d), fmaf(a, mn, d)), 0.0f);
#pragma unroll
        for (int j = 0; j < 10; ++j)
            acc[j] = fmaf(pooled, embW[cc * 10 + j], acc[j]);
    }
#pragma unroll
    for (int j = 0; j < 10; ++j) {
        float v = acc[j];
        for (int off = 16; off; off >>= 1) v += __shfl_down_sync(0xffffffffu, v, off);
        if ((tid & 31) == 0) atomicAdd(&sE[j], v);
    }
    __syncthreads();
    if (tid < 10) {
        float e = sE[tid] + embB[tid];
        eOut[b * 10 + tid] = e;
        g_e[fwd][b * 10 + tid] = e;
    }
}

// ---------------- cluster assignment (4 batches per block) ----------------
__global__ void __launch_bounds__(256)
cluster_kernel(const float* __restrict__ clu, float* __restrict__ qout,
               float* __restrict__ dout, int fwd) {
    int tid = threadIdx.x;
    __shared__ float sclu[8000];
    __shared__ float se[10];
    __shared__ float squn[800];
    __shared__ float sred[9];
    for (int s = tid; s < 8000; s += 256) sclu[s] = clu[s];
    for (int bb = 0; bb < 4; ++bb) {
        int b = blockIdx.x * 4 + bb;
        __syncthreads();
        if (tid < 10) se[tid] = g_e[fwd][b * 10 + tid];
        __syncthreads();
        float local = 0.0f;
        for (int j = tid; j < 800; j += 256) {
            float dist = 0.0f;
#pragma unroll
            for (int k = 0; k < 10; ++k) {
                float t = se[k] - sclu[j * 10 + k];
                dist = fmaf(t, t, dist);
            }
            float qun = 1.0f / (1.0f + dist);
            squn[j] = qun; local += qun;
            if (dout) dout[(size_t)b * 800 + j] = dist;
        }
        float v = local;
        for (int off = 16; off; off >>= 1) v += __shfl_down_sync(0xffffffffu, v, off);
        if ((tid & 31) == 0) sred[tid >> 5] = v;
        __syncthreads();
        if (tid == 0) {
            float t = 0.f;
            for (int w = 0; w < 8; ++w) t += sred[w];
            sred[8] = 1.0f / t;
        }
        __syncthreads();
        float inv = sred[8];
        for (int j = tid; j < 800; j += 256)
            qout[(size_t)b * 800 + j] = squn[j] * inv;
    }
}

// ---------------- pairwise distance ----------------
__global__ void sim_kernel(float* __restrict__ simOut) {
    int i = blockIdx.x * blockDim.x + threadIdx.x;
    if (i >= BATCH) return;
    float s = 0.0f;
#pragma unroll
    for (int k = 0; k < 10; ++k) {
        float t = g_e[0][i * 10 + k] - g_e[1][i * 10 + k] + 1e-6f;
        s = fmaf(t, t, s);
    }
    simOut[i] = sqrtf(s);
}

// ---------------- launch ----------------
extern "C" void kernel_launch(void* const* d_in, const int* in_sizes, int n_in,
                              void* d_out, int out_size) {
    const float* x1 = (const float*)d_in[0];
    const float* x2 = (const float*)d_in[1];
    const float* W[5]; const float* bb[5]; const float* gam[5]; const float* bet[5];
    for (int li = 0; li < 5; ++li) {
        W[li]   = (const float*)d_in[2 + li * 4 + 0];
        bb[li]  = (const float*)d_in[2 + li * 4 + 1];
        gam[li] = (const float*)d_in[2 + li * 4 + 2];
        bet[li] = (const float*)d_in[2 + li * 4 + 3];
    }
    const float* embW = (const float*)d_in[22];
    const float* embB = (const float*)d_in[23];
    const float* clu  = (const float*)d_in[24];
    float* out = (float*)d_out;

    const int SMEM64 = (64 * 68 + 64 * 64 + 2 * 64) * 4;   // 34304
    const int SM5 = SM_TOT + 1024;
    cudaFuncSetAttribute((const void*)layer5_mma,
                         cudaFuncAttributeMaxDynamicSharedMemorySize, SM5);

    const int GB = N_NODES / 64;    // 896
    const int RT = N_NODES / 128;   // 448

    prep_W5_kernel<<<512, 256>>>(W[4]);

    for (int f = 0; f < 2; ++f) {
        const float* x = f ? x2 : x1;
        zero_stats_kernel<<<5, 1024>>>();
        layer1_kernel<<<GB, 256>>>(x, W[0], bb[0]);
        gcn_gemm<64, 64><<<dim3(GB, 1), 256, SMEM64>>>(W[1], bb[1], 0, 1,
                                                       gam[0], bet[0], 0, 1, 64);
        gcn_gemm<64, 64><<<dim3(GB, 1), 256, SMEM64>>>(W[2], bb[2], 1, 0,
                                                       gam[1], bet[1], 1, 2, 64);
        gcn_gemm<64, 64><<<dim3(GB, 2), 256, SMEM64>>>(W[3], bb[3], 0, 1,
                                                       gam[2], bet[2], 2, 3, 128);
        prep_A5_kernel<<<RT, 256>>>(gam[3], bet[3]);
        layer5_mma<<<dim3(RT, 4), 256, SM5>>>(bb[4]);
        bnparams_kernel<<<4, 256>>>(gam[4], bet[4]);
        maxpool_embed_kernel<<<BATCH, 256>>>(embW, embB, out + (f ? O_E2 : O_E1), f);
        cluster_kernel<<<BATCH / 4, 256>>>(clu, out + (f ? O_C2 : O_C1),
                                           f ? (float*)nullptr : out + O_D1, f);
    }
    sim_kernel<<<16, 256>>>(out);
}

// round 10
// speedup vs baseline: 2.7542x; 1.1073x over previous
#include <cuda_runtime.h>
#include <cuda_bf16.h>
#include <math.h>
#include <stdint.h>
#include <float.h>

#define PLEN 14
#define BATCH 4096
#define N_NODES (BATCH * PLEN)   // 57344
#define TW2 (2 * N_NODES)        // both towers
#define BN_EPS 1e-5f

// Output layout: concat of (sim[B], c1[B,800], c2[B,800], e1[B,10], e2[B,10], d1[B,800])
#define O_SIM 0
#define O_C1  4096
#define O_C2  (4096 + 3276800)
#define O_E1  (4096 + 2*3276800)
#define O_E2  (O_E1 + 40960)
#define O_D1  (O_E2 + 40960)

// ---------------- scratch (device globals; no allocation) ----------------
__device__ float g_hA[(size_t)TW2 * 128];
__device__ float g_hB[(size_t)TW2 * 128];
__device__ float g_sum[2][5][1024];
__device__ float g_sq [2][5][1024];
__device__ float g_e  [2][BATCH * 10];
__device__ __nv_bfloat16 g_A5hi[(size_t)TW2 * 128];
__device__ __nv_bfloat16 g_A5lo[(size_t)TW2 * 128];
__device__ __nv_bfloat16 g_W5Th[1024 * 128];   // W5^T hi: [n][k]
__device__ __nv_bfloat16 g_W5Tl[1024 * 128];   // W5^T lo: [n][k]
// per-(molecule,col) pooling partials; molecule id is GLOBAL (0..2*BATCH-1)
__device__ float g_mxH[2 * BATCH * 1024], g_mnH[2 * BATCH * 1024];
__device__ float g_mxT[2 * BATCH * 1024], g_mnT[2 * BATCH * 1024];

// ---------------- zero the BN stat accumulators (both towers) ----------------
__global__ void zero_stats_kernel() {
    int i = blockIdx.x * blockDim.x + threadIdx.x;   // 2*5*1024
    (&g_sum[0][0][0])[i] = 0.0f;
    (&g_sq [0][0][0])[i] = 0.0f;
}

// ---------------- W5 fp32 [k][n] -> transposed bf16 hi/lo [n][k] (once) ----------------
__global__ void prep_W5_kernel(const float* __restrict__ W5) {
    int i = blockIdx.x * 256 + threadIdx.x;   // 128*1024 total
    int k = i >> 10, n = i & 1023;
    float v = W5[i];
    __nv_bfloat16 h = __float2bfloat16(v);
    g_W5Th[n * 128 + k] = h;
    g_W5Tl[n * 128 + k] = __float2bfloat16(v - __bfloat162float(h));
}

// ---------------- layer 1 (both towers) ----------------
__global__ void __launch_bounds__(256) layer1_kernel(const float* __restrict__ x1,
                                                     const float* __restrict__ x2,
                                                     const float* __restrict__ W1,
                                                     const float* __restrict__ b1) {
    __shared__ float xg[64][3];
    int tid = threadIdx.x;
    int rowBase = blockIdx.x * 64;
    int tw = rowBase >= N_NODES;
    const float* x = tw ? x2 : x1;
    int locBase = rowBase - tw * N_NODES;
    if (tid < 192) {
        int i = tid / 3, k = tid % 3;
        int nl = locBase + i, b = nl / PLEN, p = nl % PLEN;
        const float* xb = x + (size_t)b * 3 * PLEN + k * PLEN;
        float v = 0.0f;
        if (p > 0)        v += xb[p - 1];
        if (p < PLEN - 1) v += xb[p + 1];
        xg[i][k] = v;
    }
    __syncthreads();
    int c = tid & 63, rg = tid >> 6;
    float w0 = W1[c], w1 = W1[64 + c], w2 = W1[128 + c], bb = b1[c];
    float s1 = 0.0f, s2 = 0.0f;
    for (int ii = 0; ii < 16; ++ii) {
        int i = rg * 16 + ii;
        float v = fmaf(xg[i][0], w0, fmaf(xg[i][1], w1, fmaf(xg[i][2], w2, bb)));
        g_hA[(size_t)(rowBase + i) * 64 + c] = v;
        s1 += v; s2 = fmaf(v, v, s2);
    }
    atomicAdd(&g_sum[tw][0][c], s1);
    atomicAdd(&g_sq [tw][0][c], s2);
}

// ---------------- fp32 GCN GEMM (layers 2-4), in-block BN affine, both towers ----------------
template<int K, int NT>
__global__ void __launch_bounds__(256)
gcn_gemm(const float* __restrict__ W, const float* __restrict__ bias,
         int srcBuf, int dstBuf,
         const float* __restrict__ gammaP, const float* __restrict__ betaP,
         int statPrev, int statIdx, int DOUT) {
    constexpr int M = 64, TN = NT / 16, K4 = K / 4, NT4 = NT / 4, MP = M + 4;
    extern __shared__ float sm[];
    float* As = sm;
    float* Bs = As + K * MP;
    float* sA = Bs + K * NT;
    float* sD = sA + K;

    const float* prev = srcBuf ? g_hB : g_hA;
    float* out = dstBuf ? g_hB : g_hA;

    int tid = threadIdx.x, tx = tid & 15, ty = tid >> 4;
    int rowBase = blockIdx.x * M, colBase = blockIdx.y * NT;
    int tw = rowBase >= N_NODES;

    if (tid < K) {
        const float invN = 1.0f / (float)N_NODES;
        float mu  = g_sum[tw][statPrev][tid] * invN;
        float var = g_sq[tw][statPrev][tid] * invN - mu * mu;
        float s = gammaP[tid] * rsqrtf(var + BN_EPS);
        sA[tid] = s; sD[tid] = betaP[tid] - mu * s;
    }
    for (int s = tid; s < K * NT4; s += 256) {
        int k = s / NT4, j = (s - k * NT4) * 4;
        float4 w = *reinterpret_cast<const float4*>(W + (size_t)k * DOUT + colBase + j);
        *reinterpret_cast<float4*>(&Bs[k * NT + j]) = w;
    }
    __syncthreads();
    for (int s = tid; s < M * K4; s += 256) {
        int i = s / K4, kq = (s - i * K4) * 4;
        int n = rowBase + i, p = n % PLEN;
        float v0 = 0.f, v1 = 0.f, v2 = 0.f, v3 = 0.f;
        float a0 = sA[kq], a1 = sA[kq + 1], a2 = sA[kq + 2], a3 = sA[kq + 3];
        float d0 = sD[kq], d1 = sD[kq + 1], d2 = sD[kq + 2], d3 = sD[kq + 3];
        if (p > 0) {
            float4 L = *reinterpret_cast<const float4*>(prev + (size_t)(n - 1) * K + kq);
            v0 += fmaxf(fmaf(a0, L.x, d0), 0.f);
            v1 += fmaxf(fmaf(a1, L.y, d1), 0.f);
            v2 += fmaxf(fmaf(a2, L.z, d2), 0.f);
            v3 += fmaxf(fmaf(a3, L.w, d3), 0.f);
        }
        if (p < PLEN - 1) {
            float4 R = *reinterpret_cast<const float4*>(prev + (size_t)(n + 1) * K + kq);
            v0 += fmaxf(fmaf(a0, R.x, d0), 0.f);
            v1 += fmaxf(fmaf(a1, R.y, d1), 0.f);
            v2 += fmaxf(fmaf(a2, R.z, d2), 0.f);
            v3 += fmaxf(fmaf(a3, R.w, d3), 0.f);
        }
        As[(kq + 0) * MP + i] = v0;
        As[(kq + 1) * MP + i] = v1;
        As[(kq + 2) * MP + i] = v2;
        As[(kq + 3) * MP + i] = v3;
    }
    __syncthreads();

    float acc[4][TN];
#pragma unroll
    for (int r = 0; r < 4; ++r)
#pragma unroll
        for (int j = 0; j < TN; ++j) acc[r][j] = 0.0f;

    int r0 = ty * 4, c0 = tx * TN;
#pragma unroll 8
    for (int k = 0; k < K; ++k) {
        float4 a4 = *reinterpret_cast<const float4*>(&As[k * MP + r0]);
        float ar[4] = {a4.x, a4.y, a4.z, a4.w};
        float br[TN];
#pragma unroll
        for (int j = 0; j < TN; j += 4) {
            float4 b4 = *reinterpret_cast<const float4*>(&Bs[k * NT + c0 + j]);
            br[j] = b4.x; br[j + 1] = b4.y; br[j + 2] = b4.z; br[j + 3] = b4.w;
        }
#pragma unroll
        for (int r = 0; r < 4; ++r)
#pragma unroll
            for (int j = 0; j < TN; ++j)
                acc[r][j] = fmaf(ar[r], br[j], acc[r][j]);
    }
    __syncthreads();

    float bl[TN];
#pragma unroll
    for (int j = 0; j < TN; ++j) bl[j] = bias[colBase + c0 + j];

    float s1[TN], s2[TN];
#pragma unroll
    for (int j = 0; j < TN; ++j) { s1[j] = 0.f; s2[j] = 0.f; }

#pragma unroll
    for (int r = 0; r < 4; ++r) {
        float vrow[TN];
#pragma unroll
        for (int j = 0; j < TN; ++j) {
            float v = acc[r][j] + bl[j];
            vrow[j] = v; s1[j] += v; s2[j] = fmaf(v, v, s2[j]);
        }
        float* op = out + (size_t)(rowBase + r0 + r) * DOUT + colBase + c0;
#pragma unroll
        for (int j = 0; j < TN; j += 4) {
            float4 o = make_float4(vrow[j], vrow[j + 1], vrow[j + 2], vrow[j + 3]);
            *reinterpret_cast<float4*>(op + j) = o;
        }
    }
    float* red = As;
#pragma unroll
    for (int j = 0; j < TN; ++j) {
        red[ty * NT + c0 + j] = s1[j];
        red[16 * NT + ty * NT + c0 + j] = s2[j];
    }
    __syncthreads();
    if (tid < NT) {
        float t1 = 0.f, t2 = 0.f;
        for (int y = 0; y < 16; ++y) {
            t1 += red[y * NT + tid];
            t2 += red[16 * NT + y * NT + tid];
        }
        atomicAdd(&g_sum[tw][statIdx][colBase + tid], t1);
        atomicAdd(&g_sq [tw][statIdx][colBase + tid], t2);
    }
}

// ================= layer-5 tensor-core path =================

// A' = chain-agg(relu(BN4(g_hB))) -> bf16 hi/lo, affine computed per-block, both towers
__global__ void __launch_bounds__(256) prep_A5_kernel(const float* __restrict__ gamma,
                                                      const float* __restrict__ beta) {
    __shared__ float sa[128], sd[128];
    int tid = threadIdx.x;
    int rowCta = blockIdx.x * 128;
    int tw = rowCta >= N_NODES;
    if (tid < 128) {
        const float invN = 1.0f / (float)N_NODES;
        float mu  = g_sum[tw][3][tid] * invN;
        float var = g_sq[tw][3][tid] * invN - mu * mu;
        float s = gamma[tid] * rsqrtf(var + BN_EPS);
        sa[tid] = s; sd[tid] = beta[tid] - mu * s;
    }
    __syncthreads();
    for (int u = tid; u < 128 * 32; u += 256) {
        int i = u >> 5, kq = (u & 31) * 4;
        int n = rowCta + i, p = n % PLEN;
        float4 a = *reinterpret_cast<const float4*>(sa + kq);
        float4 d = *reinterpret_cast<const float4*>(sd + kq);
        float v0 = 0.f, v1 = 0.f, v2 = 0.f, v3 = 0.f;
        if (p > 0) {
            float4 L = *reinterpret_cast<const float4*>(g_hB + (size_t)(n - 1) * 128 + kq);
            v0 += fmaxf(fmaf(a.x, L.x, d.x), 0.f);
            v1 += fmaxf(fmaf(a.y, L.y, d.y), 0.f);
            v2 += fmaxf(fmaf(a.z, L.z, d.z), 0.f);
            v3 += fmaxf(fmaf(a.w, L.w, d.w), 0.f);
        }
        if (p < PLEN - 1) {
            float4 R = *reinterpret_cast<const float4*>(g_hB + (size_t)(n + 1) * 128 + kq);
            v0 += fmaxf(fmaf(a.x, R.x, d.x), 0.f);
            v1 += fmaxf(fmaf(a.y, R.y, d.y), 0.f);
            v2 += fmaxf(fmaf(a.z, R.z, d.z), 0.f);
            v3 += fmaxf(fmaf(a.w, R.w, d.w), 0.f);
        }
        __nv_bfloat16 h0 = __float2bfloat16(v0), h1 = __float2bfloat16(v1);
        __nv_bfloat16 h2 = __float2bfloat16(v2), h3 = __float2bfloat16(v3);
        __nv_bfloat16 l0 = __float2bfloat16(v0 - __bfloat162float(h0));
        __nv_bfloat16 l1 = __float2bfloat16(v1 - __bfloat162float(h1));
        __nv_bfloat16 l2 = __float2bfloat16(v2 - __bfloat162float(h2));
        __nv_bfloat16 l3 = __float2bfloat16(v3 - __bfloat162float(h3));
        size_t o = (size_t)n * 128 + kq;
        *reinterpret_cast<__nv_bfloat162*>(g_A5hi + o)     = __nv_bfloat162(h0, h1);
        *reinterpret_cast<__nv_bfloat162*>(g_A5hi + o + 2) = __nv_bfloat162(h2, h3);
        *reinterpret_cast<__nv_bfloat162*>(g_A5lo + o)     = __nv_bfloat162(l0, l1);
        *reinterpret_cast<__nv_bfloat162*>(g_A5lo + o + 2) = __nv_bfloat162(l2, l3);
    }
}

// smem layout (byte offsets); rows padded to 272B for conflict-free ldmatrix
#define L5_STRIDE 272
#define SM_AHI  0
#define SM_ALO  34816
#define SM_BHI  69632
#define SM_BLO  139264
#define SM_BIAS 208896
#define SM_TOT  209920

__device__ __forceinline__ uint32_t smem_u32(const void* p) {
    uint32_t a;
    asm("{ .reg .u64 t; cvta.to.shared.u64 t, %1; cvt.u32.u64 %0, t; }" : "=r"(a) : "l"(p));
    return a;
}
__device__ __forceinline__ void ldm4(uint32_t* r, uint32_t addr) {
    asm volatile("ldmatrix.sync.aligned.m8n8.x4.shared.b16 {%0,%1,%2,%3}, [%4];"
                 : "=r"(r[0]), "=r"(r[1]), "=r"(r[2]), "=r"(r[3]) : "r"(addr));
}
__device__ __forceinline__ void mma_bf16(float* c, const uint32_t* a,
                                         uint32_t b0, uint32_t b1) {
    asm volatile(
        "mma.sync.aligned.m16n8k16.row.col.f32.bf16.bf16.f32 "
        "{%0,%1,%2,%3}, {%4,%5,%6,%7}, {%8,%9}, {%0,%1,%2,%3};"
        : "+f"(c[0]), "+f"(c[1]), "+f"(c[2]), "+f"(c[3])
        : "r"(a[0]), "r"(a[1]), "r"(a[2]), "r"(a[3]), "r"(b0), "r"(b1));
}

__global__ void __launch_bounds__(256, 1)
layer5_mma(const float* __restrict__ bias) {
    extern __shared__ char sm5[];
    int tid = threadIdx.x, wid = tid >> 5, lane = tid & 31;
    int rowCta = blockIdx.x * 128, colBase = blockIdx.y * 256;
    int tw = rowCta >= N_NODES;
    float* sbias = reinterpret_cast<float*>(sm5 + SM_BIAS);
    sbias[tid] = bias[colBase + tid];

    {
        const uint4* aH = reinterpret_cast<const uint4*>(g_A5hi) + (size_t)rowCta * 16;
        const uint4* aL = reinterpret_cast<const uint4*>(g_A5lo) + (size_t)rowCta * 16;
#pragma unroll
        for (int t = 0; t < 8; ++t) {
            int s = tid + t * 256;
            int row = s >> 4, c = s & 15;
            *reinterpret_cast<uint4*>(sm5 + SM_AHI + row * L5_STRIDE + c * 16) = aH[s];
            *reinterpret_cast<uint4*>(sm5 + SM_ALO + row * L5_STRIDE + c * 16) = aL[s];
        }
        const uint4* bH = reinterpret_cast<const uint4*>(g_W5Th) + (size_t)colBase * 16;
        const uint4* bL = reinterpret_cast<const uint4*>(g_W5Tl) + (size_t)colBase * 16;
#pragma unroll
        for (int t = 0; t < 16; ++t) {
            int s = tid + t * 256;
            int row = s >> 4, c = s & 15;
            *reinterpret_cast<uint4*>(sm5 + SM_BHI + row * L5_STRIDE + c * 16) = bH[s];
            *reinterpret_cast<uint4*>(sm5 + SM_BLO + row * L5_STRIDE + c * 16) = bL[s];
        }
    }
    __syncthreads();

    int wm = wid >> 2, wn = wid & 3;
    int m0 = wm * 64, n0 = wn * 64;
    int quad = lane >> 3, r8 = lane & 7;
    uint32_t base = smem_u32(sm5);
    uint32_t aBase = base + SM_AHI + (uint32_t)((m0 + (quad & 1) * 8 + r8) * L5_STRIDE + (quad >> 1) * 16);
    uint32_t bBase = base + SM_BHI + (uint32_t)((n0 + (quad >> 1) * 8 + r8) * L5_STRIDE + (quad & 1) * 16);

    float acc[4][8][4];
#pragma unroll
    for (int mi = 0; mi < 4; ++mi)
#pragma unroll
        for (int nf = 0; nf < 8; ++nf)
#pragma unroll
            for (int j = 0; j < 4; ++j) acc[mi][nf][j] = 0.0f;

#pragma unroll 1
    for (int term = 0; term < 3; ++term) {
        uint32_t aB = aBase + (term == 2 ? (SM_ALO - SM_AHI) : 0u);
        uint32_t bB = bBase + (term == 1 ? (SM_BLO - SM_BHI) : 0u);
#pragma unroll
        for (int ks = 0; ks < 8; ++ks) {
            uint32_t a[4][4], b[4][4];
#pragma unroll
            for (int mi = 0; mi < 4; ++mi)
                ldm4(a[mi], aB + mi * 16 * L5_STRIDE + ks * 32);
#pragma unroll
            for (int nj = 0; nj < 4; ++nj)
                ldm4(b[nj], bB + nj * 16 * L5_STRIDE + ks * 32);
#pragma unroll
            for (int mi = 0; mi < 4; ++mi)
#pragma unroll
                for (int nf = 0; nf < 8; ++nf)
                    mma_bf16(acc[mi][nf], a[mi],
                             b[nf >> 1][(nf & 1) * 2], b[nf >> 1][(nf & 1) * 2 + 1]);
        }
    }

    // stage tile in smem (reuse A/B area), fused stats
    __syncthreads();
    float* stag = reinterpret_cast<float*>(sm5);   // [128][260] floats
    float s1[8][2], s2[8][2];
#pragma unroll
    for (int nf = 0; nf < 8; ++nf) { s1[nf][0] = s1[nf][1] = 0.f; s2[nf][0] = s2[nf][1] = 0.f; }

#pragma unroll
    for (int mi = 0; mi < 4; ++mi) {
        int rl = m0 + mi * 16 + (lane >> 2);
#pragma unroll
        for (int nf = 0; nf < 8; ++nf) {
            int cl = n0 + nf * 8 + (lane & 3) * 2;
            float b0 = sbias[cl], b1 = sbias[cl + 1];
            float c0 = acc[mi][nf][0] + b0, c1 = acc[mi][nf][1] + b1;
            float c2 = acc[mi][nf][2] + b0, c3 = acc[mi][nf][3] + b1;
            stag[rl * 260 + cl] = c0;       stag[rl * 260 + cl + 1] = c1;
            stag[(rl + 8) * 260 + cl] = c2; stag[(rl + 8) * 260 + cl + 1] = c3;
            s1[nf][0] += c0 + c2;           s1[nf][1] += c1 + c3;
            s2[nf][0] += c0 * c0 + c2 * c2; s2[nf][1] += c1 * c1 + c3 * c3;
        }
    }
#pragma unroll
    for (int nf = 0; nf < 8; ++nf)
#pragma unroll
        for (int j = 0; j < 2; ++j) {
            float v1 = s1[nf][j], v2 = s2[nf][j];
            v1 += __shfl_xor_sync(0xffffffffu, v1, 4);
            v1 += __shfl_xor_sync(0xffffffffu, v1, 8);
            v1 += __shfl_xor_sync(0xffffffffu, v1, 16);
            v2 += __shfl_xor_sync(0xffffffffu, v2, 4);
            v2 += __shfl_xor_sync(0xffffffffu, v2, 8);
            v2 += __shfl_xor_sync(0xffffffffu, v2, 16);
            if (lane < 4) {
                int col = colBase + n0 + nf * 8 + lane * 2 + j;
                atomicAdd(&g_sum[tw][4][col], v1);
                atomicAdd(&g_sq [tw][4][col], v2);
            }
        }
    __syncthreads();

    // per-molecule max/min scan -> head/tail buffers (no atomics; molecule id GLOBAL)
    int bStart = rowCta / PLEN, bEnd = (rowCta + 127) / PLEN;
    int nm = bEnd - bStart + 1;
    for (int tk = tid; tk < nm * 256; tk += 256) {
        int bi = tk >> 8, c = tk & 255;
        int b = bStart + bi;
        int r0 = b * PLEN - rowCta, r1 = r0 + PLEN;
        int a0 = r0 > 0 ? r0 : 0, a1 = r1 < 128 ? r1 : 128;
        float mx = -FLT_MAX, mn = FLT_MAX;
        for (int r = a0; r < a1; ++r) {
            float v = stag[r * 260 + c];
            mx = fmaxf(mx, v); mn = fminf(mn, v);
        }
        size_t gi = (size_t)b * 1024 + colBase + c;
        if (r0 >= 0) { g_mxH[gi] = mx; g_mnH[gi] = mn; }
        else         { g_mxT[gi] = mx; g_mnT[gi] = mn; }
    }
}

// ---------------- max-pool (partials) + inline BN affine + embedding, both towers ----------------
__global__ void __launch_bounds__(256)
maxpool_embed_kernel(const float* __restrict__ embW, const float* __restrict__ embB,
                     const float* __restrict__ gamma, const float* __restrict__ beta,
                     float* __restrict__ out) {
    int bg = blockIdx.x;              // global molecule 0..2*BATCH-1
    int tw = bg >> 12, bl = bg & (BATCH - 1);
    int tid = threadIdx.x;
    int sCta = (bg * PLEN) / 128, eCta = (bg * PLEN + PLEN - 1) / 128;
    bool split = sCta != eCta;
    __shared__ float sE[10];
    if (tid < 10) sE[tid] = 0.0f;
    __syncthreads();
    float acc[10];
#pragma unroll
    for (int j = 0; j < 10; ++j) acc[j] = 0.0f;
    const float invN = 1.0f / (float)N_NODES;
    for (int cc = tid; cc < 1024; cc += 256) {
        size_t gi = (size_t)bg * 1024 + cc;
        float mx = g_mxH[gi], mn = g_mnH[gi];
        if (split) {
            mx = fmaxf(mx, g_mxT[gi]);
            mn = fminf(mn, g_mnT[gi]);
        }
        float mu  = g_sum[tw][4][cc] * invN;
        float var = g_sq[tw][4][cc] * invN - mu * mu;
        float a = gamma[cc] * rsqrtf(var + BN_EPS);
        float d = beta[cc] - mu * a;
        float pooled = fmaxf(fmaxf(fmaf(a, mx, d), fmaf(a, mn, d)), 0.0f);
#pragma unroll
        for (int j = 0; j < 10; ++j)
            acc[j] = fmaf(pooled, embW[cc * 10 + j], acc[j]);
    }
#pragma unroll
    for (int j = 0; j < 10; ++j) {
        float v = acc[j];
        for (int off = 16; off; off >>= 1) v += __shfl_down_sync(0xffffffffu, v, off);
        if ((tid & 31) == 0) atomicAdd(&sE[j], v);
    }
    __syncthreads();
    if (tid < 10) {
        float e = sE[tid] + embB[tid];
        out[(tw ? O_E2 : O_E1) + bl * 10 + tid] = e;
        g_e[tw][bl * 10 + tid] = e;
    }
}

// ---------------- cluster assignment (4 molecules per block, both towers) ----------------
__global__ void __launch_bounds__(256)
cluster_kernel(const float* __restrict__ clu, float* __restrict__ out) {
    int tid = threadIdx.x;
    __shared__ float sclu[8000];
    __shared__ float se[10];
    __shared__ float squn[800];
    __shared__ float sred[9];
    for (int s = tid; s < 8000; s += 256) sclu[s] = clu[s];
    for (int bb = 0; bb < 4; ++bb) {
        int bg = blockIdx.x * 4 + bb;
        int tw = bg >> 12, bl = bg & (BATCH - 1);
        float* qo = out + (tw ? O_C2 : O_C1) + (size_t)bl * 800;
        float* dq = (tw == 0) ? out + O_D1 + (size_t)bl * 800 : (float*)0;
        __syncthreads();
        if (tid < 10) se[tid] = g_e[tw][bl * 10 + tid];
        __syncthreads();
        float local = 0.0f;
        for (int j = tid; j < 800; j += 256) {
            float dist = 0.0f;
#pragma unroll
            for (int k = 0; k < 10; ++k) {
                float t = se[k] - sclu[j * 10 + k];
                dist = fmaf(t, t, dist);
            }
            float qun = 1.0f / (1.0f + dist);
            squn[j] = qun; local += qun;
            if (dq) dq[j] = dist;
        }
        float v = local;
        for (int off = 16; off; off >>= 1) v += __shfl_down_sync(0xffffffffu, v, off);
        if ((tid & 31) == 0) sred[tid >> 5] = v;
        __syncthreads();
        if (tid == 0) {
            float t = 0.f;
            for (int w = 0; w < 8; ++w) t += sred[w];
            sred[8] = 1.0f / t;
        }
        __syncthreads();
        float inv = sred[8];
        for (int j = tid; j < 800; j += 256)
            qo[j] = squn[j] * inv;
    }
}

// ---------------- pairwise distance ----------------
__global__ void sim_kernel(float* __restrict__ simOut) {
    int i = blockIdx.x * blockDim.x + threadIdx.x;
    if (i >= BATCH) return;
    float s = 0.0f;
#pragma unroll
    for (int k = 0; k < 10; ++k) {
        float t = g_e[0][i * 10 + k] - g_e[1][i * 10 + k] + 1e-6f;
        s = fmaf(t, t, s);
    }
    simOut[i] = sqrtf(s);
}

// ---------------- launch ----------------
extern "C" void kernel_launch(void* const* d_in, const int* in_sizes, int n_in,
                              void* d_out, int out_size) {
    const float* x1 = (const float*)d_in[0];
    const float* x2 = (const float*)d_in[1];
    const float* W[5]; const float* bb[5]; const float* gam[5]; const float* bet[5];
    for (int li = 0; li < 5; ++li) {
        W[li]   = (const float*)d_in[2 + li * 4 + 0];
        bb[li]  = (const float*)d_in[2 + li * 4 + 1];
        gam[li] = (const float*)d_in[2 + li * 4 + 2];
        bet[li] = (const float*)d_in[2 + li * 4 + 3];
    }
    const float* embW = (const float*)d_in[22];
    const float* embB = (const float*)d_in[23];
    const float* clu  = (const float*)d_in[24];
    float* out = (float*)d_out;

    const int SMEM64 = (64 * 68 + 64 * 64 + 2 * 64) * 4;   // 34304
    const int SM5 = SM_TOT + 1024;
    cudaFuncSetAttribute((const void*)layer5_mma,
                         cudaFuncAttributeMaxDynamicSharedMemorySize, SM5);

    const int GB2 = TW2 / 64;    // 1792 row tiles (both towers)
    const int RT2 = TW2 / 128;   // 896

    prep_W5_kernel<<<512, 256>>>(W[4]);
    zero_stats_kernel<<<10, 1024>>>();
    layer1_kernel<<<GB2, 256>>>(x1, x2, W[0], bb[0]);
    gcn_gemm<64, 64><<<dim3(GB2, 1), 256, SMEM64>>>(W[1], bb[1], 0, 1,
                                                    gam[0], bet[0], 0, 1, 64);
    gcn_gemm<64, 64><<<dim3(GB2, 1), 256, SMEM64>>>(W[2], bb[2], 1, 0,
                                                    gam[1], bet[1], 1, 2, 64);
    gcn_gemm<64, 64><<<dim3(GB2, 2), 256, SMEM64>>>(W[3], bb[3], 0, 1,
                                                    gam[2], bet[2], 2, 3, 128);
    prep_A5_kernel<<<RT2, 256>>>(gam[3], bet[3]);
    layer5_mma<<<dim3(RT2, 4), 256, SM5>>>(bb[4]);
    maxpool_embed_kernel<<<2 * BATCH, 256>>>(embW, embB, gam[4], bet[4], out);
    cluster_kernel<<<2 * BATCH / 4, 256>>>(clu, out);
    sim_kernel<<<16, 256>>>(out);
}

// round 11
// speedup vs baseline: 2.8353x; 1.0295x over previous
#include <cuda_runtime.h>
#include <cuda_bf16.h>
#include <math.h>
#include <stdint.h>
#include <float.h>

#define PLEN 14
#define BATCH 4096
#define N_NODES (BATCH * PLEN)   // 57344
#define TW2 (2 * N_NODES)        // both towers
#define BN_EPS 1e-5f

// Output layout: concat of (sim[B], c1[B,800], c2[B,800], e1[B,10], e2[B,10], d1[B,800])
#define O_SIM 0
#define O_C1  4096
#define O_C2  (4096 + 3276800)
#define O_E1  (4096 + 2*3276800)
#define O_E2  (O_E1 + 40960)
#define O_D1  (O_E2 + 40960)

// ---------------- scratch (device globals; no allocation) ----------------
__device__ float g_hA[(size_t)TW2 * 128];
__device__ float g_hB[(size_t)TW2 * 128];
__device__ float g_sum[2][5][1024];
__device__ float g_sq [2][5][1024];
__device__ float g_e  [2][BATCH * 10];
__device__ __nv_bfloat16 g_A5hi[(size_t)TW2 * 128];
__device__ __nv_bfloat16 g_A5lo[(size_t)TW2 * 128];
__device__ __nv_bfloat16 g_W5Th[1024 * 128];   // W5^T hi: [n][k]
__device__ __nv_bfloat16 g_W5Tl[1024 * 128];   // W5^T lo: [n][k]
// per-(molecule,col) pooling partials; molecule id is GLOBAL (0..2*BATCH-1)
__device__ float g_mxH[2 * BATCH * 1024], g_mnH[2 * BATCH * 1024];
__device__ float g_mxT[2 * BATCH * 1024], g_mnT[2 * BATCH * 1024];

// ---------------- zero the BN stat accumulators (both towers) ----------------
__global__ void zero_stats_kernel() {
    int i = blockIdx.x * blockDim.x + threadIdx.x;   // 2*5*1024
    (&g_sum[0][0][0])[i] = 0.0f;
    (&g_sq [0][0][0])[i] = 0.0f;
}

// ---------------- W5 fp32 [k][n] -> transposed bf16 hi/lo [n][k] (once) ----------------
__global__ void prep_W5_kernel(const float* __restrict__ W5) {
    int i = blockIdx.x * 256 + threadIdx.x;   // 128*1024 total
    int k = i >> 10, n = i & 1023;
    float v = W5[i];
    __nv_bfloat16 h = __float2bfloat16(v);
    g_W5Th[n * 128 + k] = h;
    g_W5Tl[n * 128 + k] = __float2bfloat16(v - __bfloat162float(h));
}

// ---------------- layer 1 (both towers) ----------------
__global__ void __launch_bounds__(256) layer1_kernel(const float* __restrict__ x1,
                                                     const float* __restrict__ x2,
                                                     const float* __restrict__ W1,
                                                     const float* __restrict__ b1) {
    __shared__ float xg[64][3];
    int tid = threadIdx.x;
    int rowBase = blockIdx.x * 64;
    int tw = rowBase >= N_NODES;
    const float* x = tw ? x2 : x1;
    int locBase = rowBase - tw * N_NODES;
    if (tid < 192) {
        int i = tid / 3, k = tid % 3;
        int nl = locBase + i, b = nl / PLEN, p = nl % PLEN;
        const float* xb = x + (size_t)b * 3 * PLEN + k * PLEN;
        float v = 0.0f;
        if (p > 0)        v += xb[p - 1];
        if (p < PLEN - 1) v += xb[p + 1];
        xg[i][k] = v;
    }
    __syncthreads();
    int c = tid & 63, rg = tid >> 6;
    float w0 = W1[c], w1 = W1[64 + c], w2 = W1[128 + c], bb = b1[c];
    float s1 = 0.0f, s2 = 0.0f;
    for (int ii = 0; ii < 16; ++ii) {
        int i = rg * 16 + ii;
        float v = fmaf(xg[i][0], w0, fmaf(xg[i][1], w1, fmaf(xg[i][2], w2, bb)));
        g_hA[(size_t)(rowBase + i) * 64 + c] = v;
        s1 += v; s2 = fmaf(v, v, s2);
    }
    atomicAdd(&g_sum[tw][0][c], s1);
    atomicAdd(&g_sq [tw][0][c], s2);
}

// ---------------- fp32 GCN GEMM (layers 2-4), M=128 tile, in-block BN affine ----------------
// thread tile: 8 rows x TN cols (TN = NT/16), 256 threads as 16x16
template<int K, int NT>
__global__ void __launch_bounds__(256)
gcn_gemm(const float* __restrict__ W, const float* __restrict__ bias,
         int srcBuf, int dstBuf,
         const float* __restrict__ gammaP, const float* __restrict__ betaP,
         int statPrev, int statIdx, int DOUT) {
    constexpr int M = 128, TN = NT / 16, K4 = K / 4, NT4 = NT / 4, MP = M + 4;
    extern __shared__ float sm[];
    float* As = sm;                  // [K][MP] k-major
    float* Bs = As + K * MP;         // [K][NT]
    float* sA = Bs + K * NT;         // [K]
    float* sD = sA + K;              // [K]

    const float* prev = srcBuf ? g_hB : g_hA;
    float* out = dstBuf ? g_hB : g_hA;

    int tid = threadIdx.x, tx = tid & 15, ty = tid >> 4;
    int rowBase = blockIdx.x * M, colBase = blockIdx.y * NT;
    int tw = rowBase >= N_NODES;

    if (tid < K) {
        const float invN = 1.0f / (float)N_NODES;
        float mu  = g_sum[tw][statPrev][tid] * invN;
        float var = g_sq[tw][statPrev][tid] * invN - mu * mu;
        float s = gammaP[tid] * rsqrtf(var + BN_EPS);
        sA[tid] = s; sD[tid] = betaP[tid] - mu * s;
    }
    for (int s = tid; s < K * NT4; s += 256) {
        int k = s / NT4, j = (s - k * NT4) * 4;
        float4 w = *reinterpret_cast<const float4*>(W + (size_t)k * DOUT + colBase + j);
        *reinterpret_cast<float4*>(&Bs[k * NT + j]) = w;
    }
    __syncthreads();
    for (int s = tid; s < M * K4; s += 256) {
        int i = s / K4, kq = (s - i * K4) * 4;
        int n = rowBase + i, p = n % PLEN;
        float v0 = 0.f, v1 = 0.f, v2 = 0.f, v3 = 0.f;
        float a0 = sA[kq], a1 = sA[kq + 1], a2 = sA[kq + 2], a3 = sA[kq + 3];
        float d0 = sD[kq], d1 = sD[kq + 1], d2 = sD[kq + 2], d3 = sD[kq + 3];
        if (p > 0) {
            float4 L = *reinterpret_cast<const float4*>(prev + (size_t)(n - 1) * K + kq);
            v0 += fmaxf(fmaf(a0, L.x, d0), 0.f);
            v1 += fmaxf(fmaf(a1, L.y, d1), 0.f);
            v2 += fmaxf(fmaf(a2, L.z, d2), 0.f);
            v3 += fmaxf(fmaf(a3, L.w, d3), 0.f);
        }
        if (p < PLEN - 1) {
            float4 R = *reinterpret_cast<const float4*>(prev + (size_t)(n + 1) * K + kq);
            v0 += fmaxf(fmaf(a0, R.x, d0), 0.f);
            v1 += fmaxf(fmaf(a1, R.y, d1), 0.f);
            v2 += fmaxf(fmaf(a2, R.z, d2), 0.f);
            v3 += fmaxf(fmaf(a3, R.w, d3), 0.f);
        }
        As[(kq + 0) * MP + i] = v0;
        As[(kq + 1) * MP + i] = v1;
        As[(kq + 2) * MP + i] = v2;
        As[(kq + 3) * MP + i] = v3;
    }
    __syncthreads();

    float acc[8][TN];
#pragma unroll
    for (int r = 0; r < 8; ++r)
#pragma unroll
        for (int j = 0; j < TN; ++j) acc[r][j] = 0.0f;

    int r0 = ty * 8, c0 = tx * TN;
#pragma unroll 4
    for (int k = 0; k < K; ++k) {
        float4 a4a = *reinterpret_cast<const float4*>(&As[k * MP + r0]);
        float4 a4b = *reinterpret_cast<const float4*>(&As[k * MP + r0 + 4]);
        float ar[8] = {a4a.x, a4a.y, a4a.z, a4a.w, a4b.x, a4b.y, a4b.z, a4b.w};
        float br[TN];
#pragma unroll
        for (int j = 0; j < TN; j += 4) {
            float4 b4 = *reinterpret_cast<const float4*>(&Bs[k * NT + c0 + j]);
            br[j] = b4.x; br[j + 1] = b4.y; br[j + 2] = b4.z; br[j + 3] = b4.w;
        }
#pragma unroll
        for (int r = 0; r < 8; ++r)
#pragma unroll
            for (int j = 0; j < TN; ++j)
                acc[r][j] = fmaf(ar[r], br[j], acc[r][j]);
    }
    __syncthreads();

    float bl[TN];
#pragma unroll
    for (int j = 0; j < TN; ++j) bl[j] = bias[colBase + c0 + j];

    float s1[TN], s2[TN];
#pragma unroll
    for (int j = 0; j < TN; ++j) { s1[j] = 0.f; s2[j] = 0.f; }

#pragma unroll
    for (int r = 0; r < 8; ++r) {
        float vrow[TN];
#pragma unroll
        for (int j = 0; j < TN; ++j) {
            float v = acc[r][j] + bl[j];
            vrow[j] = v; s1[j] += v; s2[j] = fmaf(v, v, s2[j]);
        }
        float* op = out + (size_t)(rowBase + r0 + r) * DOUT + colBase + c0;
#pragma unroll
        for (int j = 0; j < TN; j += 4) {
            float4 o = make_float4(vrow[j], vrow[j + 1], vrow[j + 2], vrow[j + 3]);
            *reinterpret_cast<float4*>(op + j) = o;
        }
    }
    float* red = As;   // 32*NT floats <= K*MP
#pragma unroll
    for (int j = 0; j < TN; ++j) {
        red[ty * NT + c0 + j] = s1[j];
        red[16 * NT + ty * NT + c0 + j] = s2[j];
    }
    __syncthreads();
    if (tid < NT) {
        float t1 = 0.f, t2 = 0.f;
        for (int y = 0; y < 16; ++y) {
            t1 += red[y * NT + tid];
            t2 += red[16 * NT + y * NT + tid];
        }
        atomicAdd(&g_sum[tw][statIdx][colBase + tid], t1);
        atomicAdd(&g_sq [tw][statIdx][colBase + tid], t2);
    }
}

// ================= layer-5 tensor-core path =================

// A' = chain-agg(relu(BN4(g_hB))) -> bf16 hi/lo, affine computed per-block, both towers
__global__ void __launch_bounds__(256) prep_A5_kernel(const float* __restrict__ gamma,
                                                      const float* __restrict__ beta) {
    __shared__ float sa[128], sd[128];
    int tid = threadIdx.x;
    int rowCta = blockIdx.x * 128;
    int tw = rowCta >= N_NODES;
    if (tid < 128) {
        const float invN = 1.0f / (float)N_NODES;
        float mu  = g_sum[tw][3][tid] * invN;
        float var = g_sq[tw][3][tid] * invN - mu * mu;
        float s = gamma[tid] * rsqrtf(var + BN_EPS);
        sa[tid] = s; sd[tid] = beta[tid] - mu * s;
    }
    __syncthreads();
    for (int u = tid; u < 128 * 32; u += 256) {
        int i = u >> 5, kq = (u & 31) * 4;
        int n = rowCta + i, p = n % PLEN;
        float4 a = *reinterpret_cast<const float4*>(sa + kq);
        float4 d = *reinterpret_cast<const float4*>(sd + kq);
        float v0 = 0.f, v1 = 0.f, v2 = 0.f, v3 = 0.f;
        if (p > 0) {
            float4 L = *reinterpret_cast<const float4*>(g_hB + (size_t)(n - 1) * 128 + kq);
            v0 += fmaxf(fmaf(a.x, L.x, d.x), 0.f);
            v1 += fmaxf(fmaf(a.y, L.y, d.y), 0.f);
            v2 += fmaxf(fmaf(a.z, L.z, d.z), 0.f);
            v3 += fmaxf(fmaf(a.w, L.w, d.w), 0.f);
        }
        if (p < PLEN - 1) {
            float4 R = *reinterpret_cast<const float4*>(g_hB + (size_t)(n + 1) * 128 + kq);
            v0 += fmaxf(fmaf(a.x, R.x, d.x), 0.f);
            v1 += fmaxf(fmaf(a.y, R.y, d.y), 0.f);
            v2 += fmaxf(fmaf(a.z, R.z, d.z), 0.f);
            v3 += fmaxf(fmaf(a.w, R.w, d.w), 0.f);
        }
        __nv_bfloat16 h0 = __float2bfloat16(v0), h1 = __float2bfloat16(v1);
        __nv_bfloat16 h2 = __float2bfloat16(v2), h3 = __float2bfloat16(v3);
        __nv_bfloat16 l0 = __float2bfloat16(v0 - __bfloat162float(h0));
        __nv_bfloat16 l1 = __float2bfloat16(v1 - __bfloat162float(h1));
        __nv_bfloat16 l2 = __float2bfloat16(v2 - __bfloat162float(h2));
        __nv_bfloat16 l3 = __float2bfloat16(v3 - __bfloat162float(h3));
        size_t o = (size_t)n * 128 + kq;
        *reinterpret_cast<__nv_bfloat162*>(g_A5hi + o)     = __nv_bfloat162(h0, h1);
        *reinterpret_cast<__nv_bfloat162*>(g_A5hi + o + 2) = __nv_bfloat162(h2, h3);
        *reinterpret_cast<__nv_bfloat162*>(g_A5lo + o)     = __nv_bfloat162(l0, l1);
        *reinterpret_cast<__nv_bfloat162*>(g_A5lo + o + 2) = __nv_bfloat162(l2, l3);
    }
}

// smem layout (byte offsets); rows padded to 272B for conflict-free ldmatrix
#define L5_STRIDE 272
#define SM_AHI  0
#define SM_ALO  34816
#define SM_BHI  69632
#define SM_BLO  139264
#define SM_BIAS 208896
#define SM_TOT  209920

__device__ __forceinline__ uint32_t smem_u32(const void* p) {
    uint32_t a;
    asm("{ .reg .u64 t; cvta.to.shared.u64 t, %1; cvt.u32.u64 %0, t; }" : "=r"(a) : "l"(p));
    return a;
}
__device__ __forceinline__ void ldm4(uint32_t* r, uint32_t addr) {
    asm volatile("ldmatrix.sync.aligned.m8n8.x4.shared.b16 {%0,%1,%2,%3}, [%4];"
                 : "=r"(r[0]), "=r"(r[1]), "=r"(r[2]), "=r"(r[3]) : "r"(addr));
}
__device__ __forceinline__ void mma_bf16(float* c, const uint32_t* a,
                                         uint32_t b0, uint32_t b1) {
    asm volatile(
        "mma.sync.aligned.m16n8k16.row.col.f32.bf16.bf16.f32 "
        "{%0,%1,%2,%3}, {%4,%5,%6,%7}, {%8,%9}, {%0,%1,%2,%3};"
        : "+f"(c[0]), "+f"(c[1]), "+f"(c[2]), "+f"(c[3])
        : "r"(a[0]), "r"(a[1]), "r"(a[2]), "r"(a[3]), "r"(b0), "r"(b1));
}

__global__ void __launch_bounds__(256, 1)
layer5_mma(const float* __restrict__ bias) {
    extern __shared__ char sm5[];
    int tid = threadIdx.x, wid = tid >> 5, lane = tid & 31;
    int rowCta = blockIdx.x * 128, colBase = blockIdx.y * 256;
    int tw = rowCta >= N_NODES;
    float* sbias = reinterpret_cast<float*>(sm5 + SM_BIAS);
    sbias[tid] = bias[colBase + tid];

    {
        const uint4* aH = reinterpret_cast<const uint4*>(g_A5hi) + (size_t)rowCta * 16;
        const uint4* aL = reinterpret_cast<const uint4*>(g_A5lo) + (size_t)rowCta * 16;
#pragma unroll
        for (int t = 0; t < 8; ++t) {
            int s = tid + t * 256;
            int row = s >> 4, c = s & 15;
            *reinterpret_cast<uint4*>(sm5 + SM_AHI + row * L5_STRIDE + c * 16) = aH[s];
            *reinterpret_cast<uint4*>(sm5 + SM_ALO + row * L5_STRIDE + c * 16) = aL[s];
        }
        const uint4* bH = reinterpret_cast<const uint4*>(g_W5Th) + (size_t)colBase * 16;
        const uint4* bL = reinterpret_cast<const uint4*>(g_W5Tl) + (size_t)colBase * 16;
#pragma unroll
        for (int t = 0; t < 16; ++t) {
            int s = tid + t * 256;
            int row = s >> 4, c = s & 15;
            *reinterpret_cast<uint4*>(sm5 + SM_BHI + row * L5_STRIDE + c * 16) = bH[s];
            *reinterpret_cast<uint4*>(sm5 + SM_BLO + row * L5_STRIDE + c * 16) = bL[s];
        }
    }
    __syncthreads();

    int wm = wid >> 2, wn = wid & 3;
    int m0 = wm * 64, n0 = wn * 64;
    int quad = lane >> 3, r8 = lane & 7;
    uint32_t base = smem_u32(sm5);
    uint32_t aBase = base + SM_AHI + (uint32_t)((m0 + (quad & 1) * 8 + r8) * L5_STRIDE + (quad >> 1) * 16);
    uint32_t bBase = base + SM_BHI + (uint32_t)((n0 + (quad >> 1) * 8 + r8) * L5_STRIDE + (quad & 1) * 16);

    float acc[4][8][4];
#pragma unroll
    for (int mi = 0; mi < 4; ++mi)
#pragma unroll
        for (int nf = 0; nf < 8; ++nf)
#pragma unroll
            for (int j = 0; j < 4; ++j) acc[mi][nf][j] = 0.0f;

#pragma unroll 1
    for (int term = 0; term < 3; ++term) {
        uint32_t aB = aBase + (term == 2 ? (SM_ALO - SM_AHI) : 0u);
        uint32_t bB = bBase + (term == 1 ? (SM_BLO - SM_BHI) : 0u);
#pragma unroll
        for (int ks = 0; ks < 8; ++ks) {
            uint32_t a[4][4], b[4][4];
#pragma unroll
            for (int mi = 0; mi < 4; ++mi)
                ldm4(a[mi], aB + mi * 16 * L5_STRIDE + ks * 32);
#pragma unroll
            for (int nj = 0; nj < 4; ++nj)
                ldm4(b[nj], bB + nj * 16 * L5_STRIDE + ks * 32);
#pragma unroll
            for (int mi = 0; mi < 4; ++mi)
#pragma unroll
                for (int nf = 0; nf < 8; ++nf)
                    mma_bf16(acc[mi][nf], a[mi],
                             b[nf >> 1][(nf & 1) * 2], b[nf >> 1][(nf & 1) * 2 + 1]);
        }
    }

    // stage tile in smem (reuse A/B area), fused stats
    __syncthreads();
    float* stag = reinterpret_cast<float*>(sm5);   // [128][260] floats
    float s1[8][2], s2[8][2];
#pragma unroll
    for (int nf = 0; nf < 8; ++nf) { s1[nf][0] = s1[nf][1] = 0.f; s2[nf][0] = s2[nf][1] = 0.f; }

#pragma unroll
    for (int mi = 0; mi < 4; ++mi) {
        int rl = m0 + mi * 16 + (lane >> 2);
#pragma unroll
        for (int nf = 0; nf < 8; ++nf) {
            int cl = n0 + nf * 8 + (lane & 3) * 2;
            float b0 = sbias[cl], b1 = sbias[cl + 1];
            float c0 = acc[mi][nf][0] + b0, c1 = acc[mi][nf][1] + b1;
            float c2 = acc[mi][nf][2] + b0, c3 = acc[mi][nf][3] + b1;
            stag[rl * 260 + cl] = c0;       stag[rl * 260 + cl + 1] = c1;
            stag[(rl + 8) * 260 + cl] = c2; stag[(rl + 8) * 260 + cl + 1] = c3;
            s1[nf][0] += c0 + c2;           s1[nf][1] += c1 + c3;
            s2[nf][0] += c0 * c0 + c2 * c2; s2[nf][1] += c1 * c1 + c3 * c3;
        }
    }
#pragma unroll
    for (int nf = 0; nf < 8; ++nf)
#pragma unroll
        for (int j = 0; j < 2; ++j) {
            float v1 = s1[nf][j], v2 = s2[nf][j];
            v1 += __shfl_xor_sync(0xffffffffu, v1, 4);
            v1 += __shfl_xor_sync(0xffffffffu, v1, 8);
            v1 += __shfl_xor_sync(0xffffffffu, v1, 16);
            v2 += __shfl_xor_sync(0xffffffffu, v2, 4);
            v2 += __shfl_xor_sync(0xffffffffu, v2, 8);
            v2 += __shfl_xor_sync(0xffffffffu, v2, 16);
            if (lane < 4) {
                int col = colBase + n0 + nf * 8 + lane * 2 + j;
                atomicAdd(&g_sum[tw][4][col], v1);
                atomicAdd(&g_sq [tw][4][col], v2);
            }
        }
    __syncthreads();

    // per-molecule max/min scan -> head/tail buffers (no atomics; molecule id GLOBAL)
    int bStart = rowCta / PLEN, bEnd = (rowCta + 127) / PLEN;
    int nm = bEnd - bStart + 1;
    for (int tk = tid; tk < nm * 256; tk += 256) {
        int bi = tk >> 8, c = tk & 255;
        int b = bStart + bi;
        int r0 = b * PLEN - rowCta, r1 = r0 + PLEN;
        int a0 = r0 > 0 ? r0 : 0, a1 = r1 < 128 ? r1 : 128;
        float mx = -FLT_MAX, mn = FLT_MAX;
        for (int r = a0; r < a1; ++r) {
            float v = stag[r * 260 + c];
            mx = fmaxf(mx, v); mn = fminf(mn, v);
        }
        size_t gi = (size_t)b * 1024 + colBase + c;
        if (r0 >= 0) { g_mxH[gi] = mx; g_mnH[gi] = mn; }
        else         { g_mxT[gi] = mx; g_mnT[gi] = mn; }
    }
}

// ---------------- max-pool (partials) + inline BN affine + embedding, both towers ----------------
__global__ void __launch_bounds__(256)
maxpool_embed_kernel(const float* __restrict__ embW, const float* __restrict__ embB,
                     const float* __restrict__ gamma, const float* __restrict__ beta,
                     float* __restrict__ out) {
    int bg = blockIdx.x;              // global molecule 0..2*BATCH-1
    int tw = bg >> 12, bl = bg & (BATCH - 1);
    int tid = threadIdx.x;
    int sCta = (bg * PLEN) / 128, eCta = (bg * PLEN + PLEN - 1) / 128;
    bool split = sCta != eCta;
    __shared__ float sE[10];
    if (tid < 10) sE[tid] = 0.0f;
    __syncthreads();
    float acc[10];
#pragma unroll
    for (int j = 0; j < 10; ++j) acc[j] = 0.0f;
    const float invN = 1.0f / (float)N_NODES;
    for (int cc = tid; cc < 1024; cc += 256) {
        size_t gi = (size_t)bg * 1024 + cc;
        float mx = g_mxH[gi], mn = g_mnH[gi];
        if (split) {
            mx = fmaxf(mx, g_mxT[gi]);
            mn = fminf(mn, g_mnT[gi]);
        }
        float mu  = g_sum[tw][4][cc] * invN;
        float var = g_sq[tw][4][cc] * invN - mu * mu;
        float a = gamma[cc] * rsqrtf(var + BN_EPS);
        float d = beta[cc] - mu * a;
        float pooled = fmaxf(fmaxf(fmaf(a, mx, d), fmaf(a, mn, d)), 0.0f);
#pragma unroll
        for (int j = 0; j < 10; ++j)
            acc[j] = fmaf(pooled, embW[cc * 10 + j], acc[j]);
    }
#pragma unroll
    for (int j = 0; j < 10; ++j) {
        float v = acc[j];
        for (int off = 16; off; off >>= 1) v += __shfl_down_sync(0xffffffffu, v, off);
        if ((tid & 31) == 0) atomicAdd(&sE[j], v);
    }
    __syncthreads();
    if (tid < 10) {
        float e = sE[tid] + embB[tid];
        out[(tw ? O_E2 : O_E1) + bl * 10 + tid] = e;
        g_e[tw][bl * 10 + tid] = e;
    }
}

// ---------------- cluster assignment (4 molecules per block, both towers) ----------------
__global__ void __launch_bounds__(256)
cluster_kernel(const float* __restrict__ clu, float* __restrict__ out) {
    int tid = threadIdx.x;
    __shared__ float sclu[8000];
    __shared__ float se[10];
    __shared__ float squn[800];
    __shared__ float sred[9];
    for (int s = tid; s < 8000; s += 256) sclu[s] = clu[s];
    for (int bb = 0; bb < 4; ++bb) {
        int bg = blockIdx.x * 4 + bb;
        int tw = bg >> 12, bl = bg & (BATCH - 1);
        float* qo = out + (tw ? O_C2 : O_C1) + (size_t)bl * 800;
        float* dq = (tw == 0) ? out + O_D1 + (size_t)bl * 800 : (float*)0;
        __syncthreads();
        if (tid < 10) se[tid] = g_e[tw][bl * 10 + tid];
        __syncthreads();
        float local = 0.0f;
        for (int j = tid; j < 800; j += 256) {
            float dist = 0.0f;
#pragma unroll
            for (int k = 0; k < 10; ++k) {
                float t = se[k] - sclu[j * 10 + k];
                dist = fmaf(t, t, dist);
            }
            float qun = 1.0f / (1.0f + dist);
            squn[j] = qun; local += qun;
            if (dq) dq[j] = dist;
        }
        float v = local;
        for (int off = 16; off; off >>= 1) v += __shfl_down_sync(0xffffffffu, v, off);
        if ((tid & 31) == 0) sred[tid >> 5] = v;
        __syncthreads();
        if (tid == 0) {
            float t = 0.f;
            for (int w = 0; w < 8; ++w) t += sred[w];
            sred[8] = 1.0f / t;
        }
        __syncthreads();
        float inv = sred[8];
        for (int j = tid; j < 800; j += 256)
            qo[j] = squn[j] * inv;
    }
}

// ---------------- pairwise distance ----------------
__global__ void sim_kernel(float* __restrict__ simOut) {
    int i = blockIdx.x * blockDim.x + threadIdx.x;
    if (i >= BATCH) return;
    float s = 0.0f;
#pragma unroll
    for (int k = 0; k < 10; ++k) {
        float t = g_e[0][i * 10 + k] - g_e[1][i * 10 + k] + 1e-6f;
        s = fmaf(t, t, s);
    }
    simOut[i] = sqrtf(s);
}

// ---------------- launch ----------------
extern "C" void kernel_launch(void* const* d_in, const int* in_sizes, int n_in,
                              void* d_out, int out_size) {
    const float* x1 = (const float*)d_in[0];
    const float* x2 = (const float*)d_in[1];
    const float* W[5]; const float* bb[5]; const float* gam[5]; const float* bet[5];
    for (int li = 0; li < 5; ++li) {
        W[li]   = (const float*)d_in[2 + li * 4 + 0];
        bb[li]  = (const float*)d_in[2 + li * 4 + 1];
        gam[li] = (const float*)d_in[2 + li * 4 + 2];
        bet[li] = (const float*)d_in[2 + li * 4 + 3];
    }
    const float* embW = (const float*)d_in[22];
    const float* embB = (const float*)d_in[23];
    const float* clu  = (const float*)d_in[24];
    float* out = (float*)d_out;

    const int SMEM64  = (64 * 132 + 64 * 64  + 2 * 64) * 4;  // 50688
    const int SMEM128 = (64 * 132 + 64 * 128 + 2 * 64) * 4;  // 67072
    const int SM5 = SM_TOT + 1024;
    cudaFuncSetAttribute((const void*)gcn_gemm<64, 64>,
                         cudaFuncAttributeMaxDynamicSharedMemorySize, SMEM64);
    cudaFuncSetAttribute((const void*)gcn_gemm<64, 128>,
                         cudaFuncAttributeMaxDynamicSharedMemorySize, SMEM128);
    cudaFuncSetAttribute((const void*)layer5_mma,
                         cudaFuncAttributeMaxDynamicSharedMemorySize, SM5);

    const int RT2 = TW2 / 128;   // 896 row tiles of 128

    prep_W5_kernel<<<512, 256>>>(W[4]);
    zero_stats_kernel<<<10, 1024>>>();
    layer1_kernel<<<TW2 / 64, 256>>>(x1, x2, W[0], bb[0]);
    gcn_gemm<64, 64><<<dim3(RT2, 1), 256, SMEM64>>>(W[1], bb[1], 0, 1,
                                                    gam[0], bet[0], 0, 1, 64);
    gcn_gemm<64, 64><<<dim3(RT2, 1), 256, SMEM64>>>(W[2], bb[2], 1, 0,
                                                    gam[1], bet[1], 1, 2, 64);
    gcn_gemm<64, 128><<<dim3(RT2, 1), 256, SMEM128>>>(W[3], bb[3], 0, 1,
                                                      gam[2], bet[2], 2, 3, 128);
    prep_A5_kernel<<<RT2, 256>>>(gam[3], bet[3]);
    layer5_mma<<<dim3(RT2, 4), 256, SM5>>>(bb[4]);
    maxpool_embed_kernel<<<2 * BATCH, 256>>>(embW, embB, gam[4], bet[4], out);
    cluster_kernel<<<2 * BATCH / 4, 256>>>(clu, out);
    sim_kernel<<<16, 256>>>(out);
}

// round 13
// speedup vs baseline: 3.1919x; 1.1258x over previous
#include <cuda_runtime.h>
#include <cuda_bf16.h>
#include <math.h>
#include <stdint.h>
#include <float.h>

#define PLEN 14
#define BATCH 4096
#define N_NODES (BATCH * PLEN)   // 57344
#define TW2 (2 * N_NODES)        // both towers
#define BN_EPS 1e-5f

// Output layout: concat of (sim[B], c1[B,800], c2[B,800], e1[B,10], e2[B,10], d1[B,800])
#define O_SIM 0
#define O_C1  4096
#define O_C2  (4096 + 3276800)
#define O_E1  (4096 + 2*3276800)
#define O_E2  (O_E1 + 40960)
#define O_D1  (O_E2 + 40960)

// ---------------- scratch (device globals; no allocation) ----------------
__device__ float g_hA[(size_t)TW2 * 128];
__device__ float g_hB[(size_t)TW2 * 128];
__device__ float g_sum[2][5][1024];
__device__ float g_sq [2][5][1024];
__device__ float g_e  [2][BATCH * 10];
__device__ __align__(16) __nv_bfloat16 g_A5hi[(size_t)TW2 * 128];
__device__ __align__(16) __nv_bfloat16 g_A5lo[(size_t)TW2 * 128];
__device__ __align__(16) __nv_bfloat16 g_W5Th[1024 * 128];   // W5^T hi: [n][k]
__device__ __align__(16) __nv_bfloat16 g_W5Tl[1024 * 128];   // W5^T lo: [n][k]
// per-(molecule,col) pooling partials; molecule id is GLOBAL (0..2*BATCH-1)
__device__ float g_mxH[2 * BATCH * 1024], g_mnH[2 * BATCH * 1024];
__device__ float g_mxT[2 * BATCH * 1024], g_mnT[2 * BATCH * 1024];

// ---------------- zero the BN stat accumulators (both towers) ----------------
__global__ void zero_stats_kernel() {
    int i = blockIdx.x * blockDim.x + threadIdx.x;   // 2*5*1024
    (&g_sum[0][0][0])[i] = 0.0f;
    (&g_sq [0][0][0])[i] = 0.0f;
}

// ---------------- W5 fp32 [k][n] -> transposed bf16 hi/lo [n][k] (once) ----------------
__global__ void prep_W5_kernel(const float* __restrict__ W5) {
    int i = blockIdx.x * 256 + threadIdx.x;   // 128*1024 total
    int k = i >> 10, n = i & 1023;
    float v = W5[i];
    __nv_bfloat16 h = __float2bfloat16(v);
    g_W5Th[n * 128 + k] = h;
    g_W5Tl[n * 128 + k] = __float2bfloat16(v - __bfloat162float(h));
}

// ---------------- layer 1 (both towers) ----------------
__global__ void __launch_bounds__(256) layer1_kernel(const float* __restrict__ x1,
                                                     const float* __restrict__ x2,
                                                     const float* __restrict__ W1,
                                                     const float* __restrict__ b1) {
    __shared__ float xg[64][3];
    int tid = threadIdx.x;
    int rowBase = blockIdx.x * 64;
    int tw = rowBase >= N_NODES;
    const float* x = tw ? x2 : x1;
    int locBase = rowBase - tw * N_NODES;
    if (tid < 192) {
        int i = tid / 3, k = tid % 3;
        int nl = locBase + i, b = nl / PLEN, p = nl % PLEN;
        const float* xb = x + (size_t)b * 3 * PLEN + k * PLEN;
        float v = 0.0f;
        if (p > 0)        v += xb[p - 1];
        if (p < PLEN - 1) v += xb[p + 1];
        xg[i][k] = v;
    }
    __syncthreads();
    int c = tid & 63, rg = tid >> 6;
    float w0 = W1[c], w1 = W1[64 + c], w2 = W1[128 + c], bb = b1[c];
    float s1 = 0.0f, s2 = 0.0f;
    for (int ii = 0; ii < 16; ++ii) {
        int i = rg * 16 + ii;
        float v = fmaf(xg[i][0], w0, fmaf(xg[i][1], w1, fmaf(xg[i][2], w2, bb)));
        g_hA[(size_t)(rowBase + i) * 64 + c] = v;
        s1 += v; s2 = fmaf(v, v, s2);
    }
    atomicAdd(&g_sum[tw][0][c], s1);
    atomicAdd(&g_sq [tw][0][c], s2);
}

// ---------------- fp32 GCN GEMM (layers 2-4), M=128 tile, in-block BN affine ----------------
template<int K, int NT>
__global__ void __launch_bounds__(256)
gcn_gemm(const float* __restrict__ W, const float* __restrict__ bias,
         int srcBuf, int dstBuf,
         const float* __restrict__ gammaP, const float* __restrict__ betaP,
         int statPrev, int statIdx, int DOUT) {
    constexpr int M = 128, TN = NT / 16, K4 = K / 4, NT4 = NT / 4, MP = M + 4;
    extern __shared__ float sm[];
    float* As = sm;
    float* Bs = As + K * MP;
    float* sA = Bs + K * NT;
    float* sD = sA + K;

    const float* prev = srcBuf ? g_hB : g_hA;
    float* out = dstBuf ? g_hB : g_hA;

    int tid = threadIdx.x, tx = tid & 15, ty = tid >> 4;
    int rowBase = blockIdx.x * M, colBase = blockIdx.y * NT;
    int tw = rowBase >= N_NODES;

    if (tid < K) {
        const float invN = 1.0f / (float)N_NODES;
        float mu  = g_sum[tw][statPrev][tid] * invN;
        float var = g_sq[tw][statPrev][tid] * invN - mu * mu;
        float s = gammaP[tid] * rsqrtf(var + BN_EPS);
        sA[tid] = s; sD[tid] = betaP[tid] - mu * s;
    }
    for (int s = tid; s < K * NT4; s += 256) {
        int k = s / NT4, j = (s - k * NT4) * 4;
        float4 w = *reinterpret_cast<const float4*>(W + (size_t)k * DOUT + colBase + j);
        *reinterpret_cast<float4*>(&Bs[k * NT + j]) = w;
    }
    __syncthreads();
    for (int s = tid; s < M * K4; s += 256) {
        int i = s / K4, kq = (s - i * K4) * 4;
        int n = rowBase + i, p = n % PLEN;
        float v0 = 0.f, v1 = 0.f, v2 = 0.f, v3 = 0.f;
        float a0 = sA[kq], a1 = sA[kq + 1], a2 = sA[kq + 2], a3 = sA[kq + 3];
        float d0 = sD[kq], d1 = sD[kq + 1], d2 = sD[kq + 2], d3 = sD[kq + 3];
        if (p > 0) {
            float4 L = *reinterpret_cast<const float4*>(prev + (size_t)(n - 1) * K + kq);
            v0 += fmaxf(fmaf(a0, L.x, d0), 0.f);
            v1 += fmaxf(fmaf(a1, L.y, d1), 0.f);
            v2 += fmaxf(fmaf(a2, L.z, d2), 0.f);
            v3 += fmaxf(fmaf(a3, L.w, d3), 0.f);
        }
        if (p < PLEN - 1) {
            float4 R = *reinterpret_cast<const float4*>(prev + (size_t)(n + 1) * K + kq);
            v0 += fmaxf(fmaf(a0, R.x, d0), 0.f);
            v1 += fmaxf(fmaf(a1, R.y, d1), 0.f);
            v2 += fmaxf(fmaf(a2, R.z, d2), 0.f);
            v3 += fmaxf(fmaf(a3, R.w, d3), 0.f);
        }
        As[(kq + 0) * MP + i] = v0;
        As[(kq + 1) * MP + i] = v1;
        As[(kq + 2) * MP + i] = v2;
        As[(kq + 3) * MP + i] = v3;
    }
    __syncthreads();

    float acc[8][TN];
#pragma unroll
    for (int r = 0; r < 8; ++r)
#pragma unroll
        for (int j = 0; j < TN; ++j) acc[r][j] = 0.0f;

    int r0 = ty * 8, c0 = tx * TN;
#pragma unroll 4
    for (int k = 0; k < K; ++k) {
        float4 a4a = *reinterpret_cast<const float4*>(&As[k * MP + r0]);
        float4 a4b = *reinterpret_cast<const float4*>(&As[k * MP + r0 + 4]);
        float ar[8] = {a4a.x, a4a.y, a4a.z, a4a.w, a4b.x, a4b.y, a4b.z, a4b.w};
        float br[TN];
#pragma unroll
        for (int j = 0; j < TN; j += 4) {
            float4 b4 = *reinterpret_cast<const float4*>(&Bs[k * NT + c0 + j]);
            br[j] = b4.x; br[j + 1] = b4.y; br[j + 2] = b4.z; br[j + 3] = b4.w;
        }
#pragma unroll
        for (int r = 0; r < 8; ++r)
#pragma unroll
            for (int j = 0; j < TN; ++j)
                acc[r][j] = fmaf(ar[r], br[j], acc[r][j]);
    }
    __syncthreads();

    float bl[TN];
#pragma unroll
    for (int j = 0; j < TN; ++j) bl[j] = bias[colBase + c0 + j];

    float s1[TN], s2[TN];
#pragma unroll
    for (int j = 0; j < TN; ++j) { s1[j] = 0.f; s2[j] = 0.f; }

#pragma unroll
    for (int r = 0; r < 8; ++r) {
        float vrow[TN];
#pragma unroll
        for (int j = 0; j < TN; ++j) {
            float v = acc[r][j] + bl[j];
            vrow[j] = v; s1[j] += v; s2[j] = fmaf(v, v, s2[j]);
        }
        float* op = out + (size_t)(rowBase + r0 + r) * DOUT + colBase + c0;
#pragma unroll
        for (int j = 0; j < TN; j += 4) {
            float4 o = make_float4(vrow[j], vrow[j + 1], vrow[j + 2], vrow[j + 3]);
            *reinterpret_cast<float4*>(op + j) = o;
        }
    }
    float* red = As;
#pragma unroll
    for (int j = 0; j < TN; ++j) {
        red[ty * NT + c0 + j] = s1[j];
        red[16 * NT + ty * NT + c0 + j] = s2[j];
    }
    __syncthreads();
    if (tid < NT) {
        float t1 = 0.f, t2 = 0.f;
        for (int y = 0; y < 16; ++y) {
            t1 += red[y * NT + tid];
            t2 += red[16 * NT + y * NT + tid];
        }
        atomicAdd(&g_sum[tw][statIdx][colBase + tid], t1);
        atomicAdd(&g_sq [tw][statIdx][colBase + tid], t2);
    }
}

// ================= layer-5 tensor-core path =================

// A' = chain-agg(relu(BN4(g_hB))) -> bf16 hi/lo, affine computed per-block, both towers
__global__ void __launch_bounds__(256) prep_A5_kernel(const float* __restrict__ gamma,
                                                      const float* __restrict__ beta) {
    __shared__ float sa[128], sd[128];
    int tid = threadIdx.x;
    int rowCta = blockIdx.x * 128;
    int tw = rowCta >= N_NODES;
    if (tid < 128) {
        const float invN = 1.0f / (float)N_NODES;
        float mu  = g_sum[tw][3][tid] * invN;
        float var = g_sq[tw][3][tid] * invN - mu * mu;
        float s = gamma[tid] * rsqrtf(var + BN_EPS);
        sa[tid] = s; sd[tid] = beta[tid] - mu * s;
    }
    __syncthreads();
    for (int u = tid; u < 128 * 32; u += 256) {
        int i = u >> 5, kq = (u & 31) * 4;
        int n = rowCta + i, p = n % PLEN;
        float4 a = *reinterpret_cast<const float4*>(sa + kq);
        float4 d = *reinterpret_cast<const float4*>(sd + kq);
        float v0 = 0.f, v1 = 0.f, v2 = 0.f, v3 = 0.f;
        if (p > 0) {
            float4 L = *reinterpret_cast<const float4*>(g_hB + (size_t)(n - 1) * 128 + kq);
            v0 += fmaxf(fmaf(a.x, L.x, d.x), 0.f);
            v1 += fmaxf(fmaf(a.y, L.y, d.y), 0.f);
            v2 += fmaxf(fmaf(a.z, L.z, d.z), 0.f);
            v3 += fmaxf(fmaf(a.w, L.w, d.w), 0.f);
        }
        if (p < PLEN - 1) {
            float4 R = *reinterpret_cast<const float4*>(g_hB + (size_t)(n + 1) * 128 + kq);
            v0 += fmaxf(fmaf(a.x, R.x, d.x), 0.f);
            v1 += fmaxf(fmaf(a.y, R.y, d.y), 0.f);
            v2 += fmaxf(fmaf(a.z, R.z, d.z), 0.f);
            v3 += fmaxf(fmaf(a.w, R.w, d.w), 0.f);
        }
        __nv_bfloat16 h0 = __float2bfloat16(v0), h1 = __float2bfloat16(v1);
        __nv_bfloat16 h2 = __float2bfloat16(v2), h3 = __float2bfloat16(v3);
        __nv_bfloat16 l0 = __float2bfloat16(v0 - __bfloat162float(h0));
        __nv_bfloat16 l1 = __float2bfloat16(v1 - __bfloat162float(h1));
        __nv_bfloat16 l2 = __float2bfloat16(v2 - __bfloat162float(h2));
        __nv_bfloat16 l3 = __float2bfloat16(v3 - __bfloat162float(h3));
        size_t o = (size_t)n * 128 + kq;
        *reinterpret_cast<__nv_bfloat162*>(g_A5hi + o)     = __nv_bfloat162(h0, h1);
        *reinterpret_cast<__nv_bfloat162*>(g_A5hi + o + 2) = __nv_bfloat162(h2, h3);
        *reinterpret_cast<__nv_bfloat162*>(g_A5lo + o)     = __nv_bfloat162(l0, l1);
        *reinterpret_cast<__nv_bfloat162*>(g_A5lo + o + 2) = __nv_bfloat162(l2, l3);
    }
}

// smem layout (byte offsets); rows padded to 272B for conflict-free ldmatrix
// A: 64 rows (hi+lo), B: 128 rows (hi+lo), bias 128 floats. 2 CTAs/SM.
#define L5_STRIDE 272
#define SM_AHI  0
#define SM_ALO  17408
#define SM_BHI  34816
#define SM_BLO  69632
#define SM_BIAS 104448
#define SM_TOT  104960

__device__ __forceinline__ uint32_t smem_u32(const void* p) {
    uint32_t a;
    asm("{ .reg .u64 t; cvta.to.shared.u64 t, %1; cvt.u32.u64 %0, t; }" : "=r"(a) : "l"(p));
    return a;
}
__device__ __forceinline__ void ldm4(uint32_t* r, uint32_t addr) {
    asm volatile("ldmatrix.sync.aligned.m8n8.x4.shared.b16 {%0,%1,%2,%3}, [%4];"
                 : "=r"(r[0]), "=r"(r[1]), "=r"(r[2]), "=r"(r[3]) : "r"(addr));
}
__device__ __forceinline__ void mma_bf16(float* c, const uint32_t* a,
                                         uint32_t b0, uint32_t b1) {
    asm volatile(
        "mma.sync.aligned.m16n8k16.row.col.f32.bf16.bf16.f32 "
        "{%0,%1,%2,%3}, {%4,%5,%6,%7}, {%8,%9}, {%0,%1,%2,%3};"
        : "+f"(c[0]), "+f"(c[1]), "+f"(c[2]), "+f"(c[3])
        : "r"(a[0]), "r"(a[1]), "r"(a[2]), "r"(a[3]), "r"(b0), "r"(b1));
}

// grid: (8 col-blocks of 128, 224 row-groups of 512). Each CTA: B resident,
// loops 8 subtiles of 64 rows. 2 CTAs/SM for mma/epilogue overlap.
__global__ void __launch_bounds__(256, 2)
layer5_mma(const float* __restrict__ bias) {
    extern __shared__ char sm5[];
    int tid = threadIdx.x, wid = tid >> 5, lane = tid & 31;
    int colBase = blockIdx.x * 128;
    int rowCta0 = blockIdx.y * 512;
    int tw = rowCta0 >= N_NODES;
    float* sbias = reinterpret_cast<float*>(sm5 + SM_BIAS);
    if (tid < 128) sbias[tid] = bias[colBase + tid];

    // B tile once per CTA: 128 n-rows x 128 k (hi + lo)
    {
        const uint4* bH = reinterpret_cast<const uint4*>(g_W5Th) + (size_t)colBase * 16;
        const uint4* bL = reinterpret_cast<const uint4*>(g_W5Tl) + (size_t)colBase * 16;
#pragma unroll
        for (int t = 0; t < 8; ++t) {
            int s = tid + t * 256;           // 0..2047 = 128 rows x 16 uint4
            int row = s >> 4, c = s & 15;
            *reinterpret_cast<uint4*>(sm5 + SM_BHI + row * L5_STRIDE + c * 16) = bH[s];
            *reinterpret_cast<uint4*>(sm5 + SM_BLO + row * L5_STRIDE + c * 16) = bL[s];
        }
    }

    int wm = wid >> 2, wn = wid & 3;
    int m0 = wm * 32, n0 = wn * 32;
    int quad = lane >> 3, r8 = lane & 7;
    uint32_t base = smem_u32(sm5);
    uint32_t aBase = base + SM_AHI + (uint32_t)((m0 + (quad & 1) * 8 + r8) * L5_STRIDE + (quad >> 1) * 16);
    uint32_t bBase = base + SM_BHI + (uint32_t)((n0 + (quad >> 1) * 8 + r8) * L5_STRIDE + (quad & 1) * 16);

    float s1[4][2], s2[4][2];
#pragma unroll
    for (int nf = 0; nf < 4; ++nf) { s1[nf][0] = s1[nf][1] = 0.f; s2[nf][0] = s2[nf][1] = 0.f; }

#pragma unroll 1
    for (int it = 0; it < 8; ++it) {
        int rowCta = rowCta0 + it * 64;
        __syncthreads();   // prev subtile's staging reads done before A overwrite
        {
            const uint4* aH = reinterpret_cast<const uint4*>(g_A5hi) + (size_t)rowCta * 16;
            const uint4* aL = reinterpret_cast<const uint4*>(g_A5lo) + (size_t)rowCta * 16;
#pragma unroll
            for (int t = 0; t < 4; ++t) {
                int s = tid + t * 256;       // 0..1023 = 64 rows x 16 uint4
                int row = s >> 4, c = s & 15;
                *reinterpret_cast<uint4*>(sm5 + SM_AHI + row * L5_STRIDE + c * 16) = aH[s];
                *reinterpret_cast<uint4*>(sm5 + SM_ALO + row * L5_STRIDE + c * 16) = aL[s];
            }
        }
        __syncthreads();

        float acc[2][4][4];
#pragma unroll
        for (int mi = 0; mi < 2; ++mi)
#pragma unroll
            for (int nf = 0; nf < 4; ++nf)
#pragma unroll
                for (int j = 0; j < 4; ++j) acc[mi][nf][j] = 0.0f;

#pragma unroll 1
        for (int term = 0; term < 3; ++term) {
            uint32_t aB = aBase + (term == 2 ? (SM_ALO - SM_AHI) : 0u);
            uint32_t bB = bBase + (term == 1 ? (SM_BLO - SM_BHI) : 0u);
#pragma unroll
            for (int ks = 0; ks < 8; ++ks) {
                uint32_t a[2][4], b[2][4];
#pragma unroll
                for (int mi = 0; mi < 2; ++mi)
                    ldm4(a[mi], aB + mi * 16 * L5_STRIDE + ks * 32);
#pragma unroll
                for (int nj = 0; nj < 2; ++nj)
                    ldm4(b[nj], bB + nj * 16 * L5_STRIDE + ks * 32);
#pragma unroll
                for (int mi = 0; mi < 2; ++mi)
#pragma unroll
                    for (int nf = 0; nf < 4; ++nf)
                        mma_bf16(acc[mi][nf], a[mi],
                                 b[nf >> 1][(nf & 1) * 2], b[nf >> 1][(nf & 1) * 2 + 1]);
            }
        }
        __syncthreads();   // all warps done with ldmatrix before staging into A region

        // stage 64x128 tile (+bias) into A smem region; accumulate stats
        float* stag = reinterpret_cast<float*>(sm5);   // [64][132]
#pragma unroll
        for (int mi = 0; mi < 2; ++mi) {
            int rl = m0 + mi * 16 + (lane >> 2);
#pragma unroll
            for (int nf = 0; nf < 4; ++nf) {
                int cl = n0 + nf * 8 + (lane & 3) * 2;
                float b0 = sbias[cl], b1 = sbias[cl + 1];
                float c0 = acc[mi][nf][0] + b0, c1 = acc[mi][nf][1] + b1;
                float c2 = acc[mi][nf][2] + b0, c3 = acc[mi][nf][3] + b1;
                stag[rl * 132 + cl] = c0;       stag[rl * 132 + cl + 1] = c1;
                stag[(rl + 8) * 132 + cl] = c2; stag[(rl + 8) * 132 + cl + 1] = c3;
                s1[nf][0] += c0 + c2;           s1[nf][1] += c1 + c3;
                s2[nf][0] += c0 * c0 + c2 * c2; s2[nf][1] += c1 * c1 + c3 * c3;
            }
        }
        __syncthreads();

        // per-molecule max/min scan -> head/tail buffers (no atomics; molecule id GLOBAL)
        int bStart = rowCta / PLEN, bEnd = (rowCta + 63) / PLEN;
        int nm = bEnd - bStart + 1;
        for (int tk = tid; tk < nm * 128; tk += 256) {
            int bi = tk >> 7, c = tk & 127;
            int b = bStart + bi;
            int r0 = b * PLEN - rowCta, r1 = r0 + PLEN;
            int a0 = r0 > 0 ? r0 : 0, a1 = r1 < 64 ? r1 : 64;
            float mx = -FLT_MAX, mn = FLT_MAX;
            for (int r = a0; r < a1; ++r) {
                float v = stag[r * 132 + c];
                mx = fmaxf(mx, v); mn = fminf(mn, v);
            }
            size_t gi = (size_t)b * 1024 + colBase + c;
            if (r0 >= 0) { g_mxH[gi] = mx; g_mnH[gi] = mn; }
            else         { g_mxT[gi] = mx; g_mnT[gi] = mn; }
        }
    }

    // stats atomics once per CTA (accumulated over all 8 subtiles)
#pragma unroll
    for (int nf = 0; nf < 4; ++nf)
#pragma unroll
        for (int j = 0; j < 2; ++j) {
            float v1 = s1[nf][j], v2 = s2[nf][j];
            v1 += __shfl_xor_sync(0xffffffffu, v1, 4);
            v1 += __shfl_xor_sync(0xffffffffu, v1, 8);
            v1 += __shfl_xor_sync(0xffffffffu, v1, 16);
            v2 += __shfl_xor_sync(0xffffffffu, v2, 4);
            v2 += __shfl_xor_sync(0xffffffffu, v2, 8);
            v2 += __shfl_xor_sync(0xffffffffu, v2, 16);
            if (lane < 4) {
                int col = colBase + n0 + nf * 8 + lane * 2 + j;
                atomicAdd(&g_sum[tw][4][col], v1);
                atomicAdd(&g_sq [tw][4][col], v2);
            }
        }
}

// ---------------- max-pool (partials) + inline BN affine + embedding, both towers ----------------
__global__ void __launch_bounds__(256)
maxpool_embed_kernel(const float* __restrict__ embW, const float* __restrict__ embB,
                     const float* __restrict__ gamma, const float* __restrict__ beta,
                     float* __restrict__ out) {
    int bg = blockIdx.x;              // global molecule 0..2*BATCH-1
    int tw = bg >> 12, bl = bg & (BATCH - 1);
    int tid = threadIdx.x;
    int sCta = (bg * PLEN) / 64, eCta = (bg * PLEN + PLEN - 1) / 64;
    bool split = sCta != eCta;
    __shared__ float sE[10];
    if (tid < 10) sE[tid] = 0.0f;
    __syncthreads();
    float acc[10];
#pragma unroll
    for (int j = 0; j < 10; ++j) acc[j] = 0.0f;
    const float invN = 1.0f / (float)N_NODES;
    for (int cc = tid; cc < 1024; cc += 256) {
        size_t gi = (size_t)bg * 1024 + cc;
        float mx = g_mxH[gi], mn = g_mnH[gi];
        if (split) {
            mx = fmaxf(mx, g_mxT[gi]);
            mn = fminf(mn, g_mnT[gi]);
        }
        float mu  = g_sum[tw][4][cc] * invN;
        float var = g_sq[tw][4][cc] * invN - mu * mu;
        float a = gamma[cc] * rsqrtf(var + BN_EPS);
        float d = beta[cc] - mu * a;
        float pooled = fmaxf(fmaxf(fmaf(a, mx, d), fmaf(a, mn, d)), 0.0f);
#pragma unroll
        for (int j = 0; j < 10; ++j)
            acc[j] = fmaf(pooled, embW[cc * 10 + j], acc[j]);
    }
#pragma unroll
    for (int j = 0; j < 10; ++j) {
        float v = acc[j];
        for (int off = 16; off; off >>= 1) v += __shfl_down_sync(0xffffffffu, v, off);
        if ((tid & 31) == 0) atomicAdd(&sE[j], v);
    }
    __syncthreads();
    if (tid < 10) {
        float e = sE[tid] + embB[tid];
        out[(tw ? O_E2 : O_E1) + bl * 10 + tid] = e;
        g_e[tw][bl * 10 + tid] = e;
    }
}

// ---------------- cluster assignment (4 molecules per block, both towers) ----------------
__global__ void __launch_bounds__(256)
cluster_kernel(const float* __restrict__ clu, float* __restrict__ out) {
    int tid = threadIdx.x;
    __shared__ float sclu[8000];
    __shared__ float se[10];
    __shared__ float squn[800];
    __shared__ float sred[9];
    for (int s = tid; s < 8000; s += 256) sclu[s] = clu[s];
    for (int bb = 0; bb < 4; ++bb) {
        int bg = blockIdx.x * 4 + bb;
        int tw = bg >> 12, bl = bg & (BATCH - 1);
        float* qo = out + (tw ? O_C2 : O_C1) + (size_t)bl * 800;
        float* dq = (tw == 0) ? out + O_D1 + (size_t)bl * 800 : (float*)0;
        __syncthreads();
        if (tid < 10) se[tid] = g_e[tw][bl * 10 + tid];
        __syncthreads();
        float local = 0.0f;
        for (int j = tid; j < 800; j += 256) {
            float dist = 0.0f;
#pragma unroll
            for (int k = 0; k < 10; ++k) {
                float t = se[k] - sclu[j * 10 + k];
                dist = fmaf(t, t, dist);
            }
            float qun = 1.0f / (1.0f + dist);
            squn[j] = qun; local += qun;
            if (dq) dq[j] = dist;
        }
        float v = local;
        for (int off = 16; off; off >>= 1) v += __shfl_down_sync(0xffffffffu, v, off);
        if ((tid & 31) == 0) sred[tid >> 5] = v;
        __syncthreads();
        if (tid == 0) {
            float t = 0.f;
            for (int w = 0; w < 8; ++w) t += sred[w];
            sred[8] = 1.0f / t;
        }
        __syncthreads();
        float inv = sred[8];
        for (int j = tid; j < 800; j += 256)
            qo[j] = squn[j] * inv;
    }
}

// ---------------- pairwise distance ----------------
__global__ void sim_kernel(float* __restrict__ simOut) {
    int i = blockIdx.x * blockDim.x + threadIdx.x;
    if (i >= BATCH) return;
    float s = 0.0f;
#pragma unroll
    for (int k = 0; k < 10; ++k) {
        float t = g_e[0][i * 10 + k] - g_e[1][i * 10 + k] + 1e-6f;
        s = fmaf(t, t, s);
    }
    simOut[i] = sqrtf(s);
}

// ---------------- launch ----------------
extern "C" void kernel_launch(void* const* d_in, const int* in_sizes, int n_in,
                              void* d_out, int out_size) {
    const float* x1 = (const float*)d_in[0];
    const float* x2 = (const float*)d_in[1];
    const float* W[5]; const float* bb[5]; const float* gam[5]; const float* bet[5];
    for (int li = 0; li < 5; ++li) {
        W[li]   = (const float*)d_in[2 + li * 4 + 0];
        bb[li]  = (const float*)d_in[2 + li * 4 + 1];
        gam[li] = (const float*)d_in[2 + li * 4 + 2];
        bet[li] = (const float*)d_in[2 + li * 4 + 3];
    }
    const float* embW = (const float*)d_in[22];
    const float* embB = (const float*)d_in[23];
    const float* clu  = (const float*)d_in[24];
    float* out = (float*)d_out;

    const int SMEM64  = (64 * 132 + 64 * 64  + 2 * 64) * 4;  // 50688
    const int SMEM128 = (64 * 132 + 64 * 128 + 2 * 64) * 4;  // 67072
    cudaFuncSetAttribute((const void*)gcn_gemm<64, 64>,
                         cudaFuncAttributeMaxDynamicSharedMemorySize, SMEM64);
    cudaFuncSetAttribute((const void*)gcn_gemm<64, 128>,
                         cudaFuncAttributeMaxDynamicSharedMemorySize, SMEM128);
    cudaFuncSetAttribute((const void*)layer5_mma,
                         cudaFuncAttributeMaxDynamicSharedMemorySize, SM_TOT);

    const int RT2 = TW2 / 128;   // 896 row tiles of 128

    prep_W5_kernel<<<512, 256>>>(W[4]);
    zero_stats_kernel<<<10, 1024>>>();
    layer1_kernel<<<TW2 / 64, 256>>>(x1, x2, W[0], bb[0]);
    gcn_gemm<64, 64><<<dim3(RT2, 1), 256, SMEM64>>>(W[1], bb[1], 0, 1,
                                                    gam[0], bet[0], 0, 1, 64);
    gcn_gemm<64, 64><<<dim3(RT2, 1), 256, SMEM64>>>(W[2], bb[2], 1, 0,
                                                    gam[1], bet[1], 1, 2, 64);
    gcn_gemm<64, 128><<<dim3(RT2, 1), 256, SMEM128>>>(W[3], bb[3], 0, 1,
                                                      gam[2], bet[2], 2, 3, 128);
    prep_A5_kernel<<<RT2, 256>>>(gam[3], bet[3]);
    layer5_mma<<<dim3(8, TW2 / 512), 256, SM_TOT>>>(bb[4]);
    maxpool_embed_kernel<<<2 * BATCH, 256>>>(embW, embB, gam[4], bet[4], out);
    cluster_kernel<<<2 * BATCH / 4, 256>>>(clu, out);
    sim_kernel<<<16, 256>>>(out);
}

// round 14
// speedup vs baseline: 4.1995x; 1.3157x over previous
#include <cuda_runtime.h>
#include <cuda_fp16.h>
#include <math.h>
#include <stdint.h>
#include <float.h>

#define PLEN 14
#define BATCH 4096
#define N_NODES (BATCH * PLEN)   // 57344
#define TW2 (2 * N_NODES)        // both towers
#define BN_EPS 1e-5f

// Output layout: concat of (sim[B], c1[B,800], c2[B,800], e1[B,10], e2[B,10], d1[B,800])
#define O_SIM 0
#define O_C1  4096
#define O_C2  (4096 + 3276800)
#define O_E1  (4096 + 2*3276800)
#define O_E2  (O_E1 + 40960)
#define O_D1  (O_E2 + 40960)

// ---------------- scratch (device globals; no allocation) ----------------
__device__ float g_hA[(size_t)TW2 * 128];
__device__ float g_hB[(size_t)TW2 * 128];
__device__ float g_sum[2][5][1024];
__device__ float g_sq [2][5][1024];
__device__ float g_e  [2][BATCH * 10];
__device__ __align__(16) __half g_A5[(size_t)TW2 * 128];     // fp16 A for layer5
__device__ __align__(16) __half g_W5T[1024 * 128];           // W5^T fp16: [n][k]
// per-(molecule,col) pooling partials; molecule id is GLOBAL (0..2*BATCH-1)
__device__ float g_mxH[2 * BATCH * 1024], g_mnH[2 * BATCH * 1024];
__device__ float g_mxT[2 * BATCH * 1024], g_mnT[2 * BATCH * 1024];

// ---------------- zero the BN stat accumulators (both towers) ----------------
__global__ void zero_stats_kernel() {
    int i = blockIdx.x * blockDim.x + threadIdx.x;   // 2*5*1024
    (&g_sum[0][0][0])[i] = 0.0f;
    (&g_sq [0][0][0])[i] = 0.0f;
}

// ---------------- W5 fp32 [k][n] -> transposed fp16 [n][k] (once) ----------------
__global__ void prep_W5_kernel(const float* __restrict__ W5) {
    int i = blockIdx.x * 256 + threadIdx.x;   // 128*1024 total
    int k = i >> 10, n = i & 1023;
    g_W5T[n * 128 + k] = __float2half(W5[i]);
}

// ---------------- layer 1 (both towers) ----------------
__global__ void __launch_bounds__(256) layer1_kernel(const float* __restrict__ x1,
                                                     const float* __restrict__ x2,
                                                     const float* __restrict__ W1,
                                                     const float* __restrict__ b1) {
    __shared__ float xg[64][3];
    int tid = threadIdx.x;
    int rowBase = blockIdx.x * 64;
    int tw = rowBase >= N_NODES;
    const float* x = tw ? x2 : x1;
    int locBase = rowBase - tw * N_NODES;
    if (tid < 192) {
        int i = tid / 3, k = tid % 3;
        int nl = locBase + i, b = nl / PLEN, p = nl % PLEN;
        const float* xb = x + (size_t)b * 3 * PLEN + k * PLEN;
        float v = 0.0f;
        if (p > 0)        v += xb[p - 1];
        if (p < PLEN - 1) v += xb[p + 1];
        xg[i][k] = v;
    }
    __syncthreads();
    int c = tid & 63, rg = tid >> 6;
    float w0 = W1[c], w1 = W1[64 + c], w2 = W1[128 + c], bb = b1[c];
    float s1 = 0.0f, s2 = 0.0f;
    for (int ii = 0; ii < 16; ++ii) {
        int i = rg * 16 + ii;
        float v = fmaf(xg[i][0], w0, fmaf(xg[i][1], w1, fmaf(xg[i][2], w2, bb)));
        g_hA[(size_t)(rowBase + i) * 64 + c] = v;
        s1 += v; s2 = fmaf(v, v, s2);
    }
    atomicAdd(&g_sum[tw][0][c], s1);
    atomicAdd(&g_sq [tw][0][c], s2);
}

// ---------------- fp32 GCN GEMM (layers 2-4), M=128 tile, in-block BN affine ----------------
template<int K, int NT>
__global__ void __launch_bounds__(256)
gcn_gemm(const float* __restrict__ W, const float* __restrict__ bias,
         int srcBuf, int dstBuf,
         const float* __restrict__ gammaP, const float* __restrict__ betaP,
         int statPrev, int statIdx, int DOUT) {
    constexpr int M = 128, TN = NT / 16, K4 = K / 4, NT4 = NT / 4, MP = M + 4;
    extern __shared__ float sm[];
    float* As = sm;
    float* Bs = As + K * MP;
    float* sA = Bs + K * NT;
    float* sD = sA + K;

    const float* prev = srcBuf ? g_hB : g_hA;
    float* out = dstBuf ? g_hB : g_hA;

    int tid = threadIdx.x, tx = tid & 15, ty = tid >> 4;
    int rowBase = blockIdx.x * M, colBase = blockIdx.y * NT;
    int tw = rowBase >= N_NODES;

    if (tid < K) {
        const float invN = 1.0f / (float)N_NODES;
        float mu  = g_sum[tw][statPrev][tid] * invN;
        float var = g_sq[tw][statPrev][tid] * invN - mu * mu;
        float s = gammaP[tid] * rsqrtf(var + BN_EPS);
        sA[tid] = s; sD[tid] = betaP[tid] - mu * s;
    }
    for (int s = tid; s < K * NT4; s += 256) {
        int k = s / NT4, j = (s - k * NT4) * 4;
        float4 w = *reinterpret_cast<const float4*>(W + (size_t)k * DOUT + colBase + j);
        *reinterpret_cast<float4*>(&Bs[k * NT + j]) = w;
    }
    __syncthreads();
    for (int s = tid; s < M * K4; s += 256) {
        int i = s / K4, kq = (s - i * K4) * 4;
        int n = rowBase + i, p = n % PLEN;
        float v0 = 0.f, v1 = 0.f, v2 = 0.f, v3 = 0.f;
        float a0 = sA[kq], a1 = sA[kq + 1], a2 = sA[kq + 2], a3 = sA[kq + 3];
        float d0 = sD[kq], d1 = sD[kq + 1], d2 = sD[kq + 2], d3 = sD[kq + 3];
        if (p > 0) {
            float4 L = *reinterpret_cast<const float4*>(prev + (size_t)(n - 1) * K + kq);
            v0 += fmaxf(fmaf(a0, L.x, d0), 0.f);
            v1 += fmaxf(fmaf(a1, L.y, d1), 0.f);
            v2 += fmaxf(fmaf(a2, L.z, d2), 0.f);
            v3 += fmaxf(fmaf(a3, L.w, d3), 0.f);
        }
        if (p < PLEN - 1) {
            float4 R = *reinterpret_cast<const float4*>(prev + (size_t)(n + 1) * K + kq);
            v0 += fmaxf(fmaf(a0, R.x, d0), 0.f);
            v1 += fmaxf(fmaf(a1, R.y, d1), 0.f);
            v2 += fmaxf(fmaf(a2, R.z, d2), 0.f);
            v3 += fmaxf(fmaf(a3, R.w, d3), 0.f);
        }
        As[(kq + 0) * MP + i] = v0;
        As[(kq + 1) * MP + i] = v1;
        As[(kq + 2) * MP + i] = v2;
        As[(kq + 3) * MP + i] = v3;
    }
    __syncthreads();

    float acc[8][TN];
#pragma unroll
    for (int r = 0; r < 8; ++r)
#pragma unroll
        for (int j = 0; j < TN; ++j) acc[r][j] = 0.0f;

    int r0 = ty * 8, c0 = tx * TN;
#pragma unroll 4
    for (int k = 0; k < K; ++k) {
        float4 a4a = *reinterpret_cast<const float4*>(&As[k * MP + r0]);
        float4 a4b = *reinterpret_cast<const float4*>(&As[k * MP + r0 + 4]);
        float ar[8] = {a4a.x, a4a.y, a4a.z, a4a.w, a4b.x, a4b.y, a4b.z, a4b.w};
        float br[TN];
#pragma unroll
        for (int j = 0; j < TN; j += 4) {
            float4 b4 = *reinterpret_cast<const float4*>(&Bs[k * NT + c0 + j]);
            br[j] = b4.x; br[j + 1] = b4.y; br[j + 2] = b4.z; br[j + 3] = b4.w;
        }
#pragma unroll
        for (int r = 0; r < 8; ++r)
#pragma unroll
            for (int j = 0; j < TN; ++j)
                acc[r][j] = fmaf(ar[r], br[j], acc[r][j]);
    }
    __syncthreads();

    float bl[TN];
#pragma unroll
    for (int j = 0; j < TN; ++j) bl[j] = bias[colBase + c0 + j];

    float s1[TN], s2[TN];
#pragma unroll
    for (int j = 0; j < TN; ++j) { s1[j] = 0.f; s2[j] = 0.f; }

#pragma unroll
    for (int r = 0; r < 8; ++r) {
        float vrow[TN];
#pragma unroll
        for (int j = 0; j < TN; ++j) {
            float v = acc[r][j] + bl[j];
            vrow[j] = v; s1[j] += v; s2[j] = fmaf(v, v, s2[j]);
        }
        float* op = out + (size_t)(rowBase + r0 + r) * DOUT + colBase + c0;
#pragma unroll
        for (int j = 0; j < TN; j += 4) {
            float4 o = make_float4(vrow[j], vrow[j + 1], vrow[j + 2], vrow[j + 3]);
            *reinterpret_cast<float4*>(op + j) = o;
        }
    }
    float* red = As;
#pragma unroll
    for (int j = 0; j < TN; ++j) {
        red[ty * NT + c0 + j] = s1[j];
        red[16 * NT + ty * NT + c0 + j] = s2[j];
    }
    __syncthreads();
    if (tid < NT) {
        float t1 = 0.f, t2 = 0.f;
        for (int y = 0; y < 16; ++y) {
            t1 += red[y * NT + tid];
            t2 += red[16 * NT + y * NT + tid];
        }
        atomicAdd(&g_sum[tw][statIdx][colBase + tid], t1);
        atomicAdd(&g_sq [tw][statIdx][colBase + tid], t2);
    }
}

// ================= layer-5 tensor-core path (single-term fp16) =================

// A' = chain-agg(relu(BN4(g_hB))) -> fp16, affine computed per-block, both towers
__global__ void __launch_bounds__(256) prep_A5_kernel(const float* __restrict__ gamma,
                                                      const float* __restrict__ beta) {
    __shared__ float sa[128], sd[128];
    int tid = threadIdx.x;
    int rowCta = blockIdx.x * 128;
    int tw = rowCta >= N_NODES;
    if (tid < 128) {
        const float invN = 1.0f / (float)N_NODES;
        float mu  = g_sum[tw][3][tid] * invN;
        float var = g_sq[tw][3][tid] * invN - mu * mu;
        float s = gamma[tid] * rsqrtf(var + BN_EPS);
        sa[tid] = s; sd[tid] = beta[tid] - mu * s;
    }
    __syncthreads();
    for (int u = tid; u < 128 * 32; u += 256) {
        int i = u >> 5, kq = (u & 31) * 4;
        int n = rowCta + i, p = n % PLEN;
        float4 a = *reinterpret_cast<const float4*>(sa + kq);
        float4 d = *reinterpret_cast<const float4*>(sd + kq);
        float v0 = 0.f, v1 = 0.f, v2 = 0.f, v3 = 0.f;
        if (p > 0) {
            float4 L = *reinterpret_cast<const float4*>(g_hB + (size_t)(n - 1) * 128 + kq);
            v0 += fmaxf(fmaf(a.x, L.x, d.x), 0.f);
            v1 += fmaxf(fmaf(a.y, L.y, d.y), 0.f);
            v2 += fmaxf(fmaf(a.z, L.z, d.z), 0.f);
            v3 += fmaxf(fmaf(a.w, L.w, d.w), 0.f);
        }
        if (p < PLEN - 1) {
            float4 R = *reinterpret_cast<const float4*>(g_hB + (size_t)(n + 1) * 128 + kq);
            v0 += fmaxf(fmaf(a.x, R.x, d.x), 0.f);
            v1 += fmaxf(fmaf(a.y, R.y, d.y), 0.f);
            v2 += fmaxf(fmaf(a.z, R.z, d.z), 0.f);
            v3 += fmaxf(fmaf(a.w, R.w, d.w), 0.f);
        }
        size_t o = (size_t)n * 128 + kq;
        __half2* ph = reinterpret_cast<__half2*>(g_A5 + o);
        ph[0] = __halves2half2(__float2half(v0), __float2half(v1));
        ph[1] = __halves2half2(__float2half(v2), __float2half(v3));
    }
}

// smem layout (byte offsets); rows padded to 272B for conflict-free ldmatrix
// A: 64 rows fp16, B: 128 rows fp16, staging [64][132] fp32, bias. 2 CTAs/SM.
#define L5_STRIDE 272
#define SM_A    0
#define SM_BH   17408
#define SM_STAG 52224
#define SM_BIAS 86016
#define SM_TOT  86528

__device__ __forceinline__ uint32_t smem_u32(const void* p) {
    uint32_t a;
    asm("{ .reg .u64 t; cvta.to.shared.u64 t, %1; cvt.u32.u64 %0, t; }" : "=r"(a) : "l"(p));
    return a;
}
__device__ __forceinline__ void ldm4(uint32_t* r, uint32_t addr) {
    asm volatile("ldmatrix.sync.aligned.m8n8.x4.shared.b16 {%0,%1,%2,%3}, [%4];"
                 : "=r"(r[0]), "=r"(r[1]), "=r"(r[2]), "=r"(r[3]) : "r"(addr));
}
__device__ __forceinline__ void mma_f16(float* c, const uint32_t* a,
                                        uint32_t b0, uint32_t b1) {
    asm volatile(
        "mma.sync.aligned.m16n8k16.row.col.f32.f16.f16.f32 "
        "{%0,%1,%2,%3}, {%4,%5,%6,%7}, {%8,%9}, {%0,%1,%2,%3};"
        : "+f"(c[0]), "+f"(c[1]), "+f"(c[2]), "+f"(c[3])
        : "r"(a[0]), "r"(a[1]), "r"(a[2]), "r"(a[3]), "r"(b0), "r"(b1));
}

// grid: (8 col-blocks of 128, 224 row-groups of 512). Each CTA: B resident,
// loops 8 subtiles of 64 rows. 2 CTAs/SM.
__global__ void __launch_bounds__(256, 2)
layer5_mma(const float* __restrict__ bias) {
    extern __shared__ char sm5[];
    int tid = threadIdx.x, wid = tid >> 5, lane = tid & 31;
    int colBase = blockIdx.x * 128;
    int rowCta0 = blockIdx.y * 512;
    int tw = rowCta0 >= N_NODES;
    float* sbias = reinterpret_cast<float*>(sm5 + SM_BIAS);
    if (tid < 128) sbias[tid] = bias[colBase + tid];

    // B tile once per CTA: 128 n-rows x 128 k fp16
    {
        const uint4* bp = reinterpret_cast<const uint4*>(g_W5T) + (size_t)colBase * 16;
#pragma unroll
        for (int t = 0; t < 8; ++t) {
            int s = tid + t * 256;           // 0..2047 = 128 rows x 16 uint4
            int row = s >> 4, c = s & 15;
            *reinterpret_cast<uint4*>(sm5 + SM_BH + row * L5_STRIDE + c * 16) = bp[s];
        }
    }

    int wm = wid >> 2, wn = wid & 3;
    int m0 = wm * 32, n0 = wn * 32;
    int quad = lane >> 3, r8 = lane & 7;
    uint32_t base = smem_u32(sm5);
    uint32_t aBase = base + SM_A + (uint32_t)((m0 + (quad & 1) * 8 + r8) * L5_STRIDE + (quad >> 1) * 16);
    uint32_t bBase = base + SM_BH + (uint32_t)((n0 + (quad >> 1) * 8 + r8) * L5_STRIDE + (quad & 1) * 16);

    float s1[4][2], s2[4][2];
#pragma unroll
    for (int nf = 0; nf < 4; ++nf) { s1[nf][0] = s1[nf][1] = 0.f; s2[nf][0] = s2[nf][1] = 0.f; }

    float* stag = reinterpret_cast<float*>(sm5 + SM_STAG);   // [64][132]

#pragma unroll 1
    for (int it = 0; it < 8; ++it) {
        int rowCta = rowCta0 + it * 64;
        __syncthreads();   // prev iter fully done (A reads, staging reads) before overwrite
        {
            const uint4* ap = reinterpret_cast<const uint4*>(g_A5) + (size_t)rowCta * 16;
#pragma unroll
            for (int t = 0; t < 4; ++t) {
                int s = tid + t * 256;       // 0..1023 = 64 rows x 16 uint4
                int row = s >> 4, c = s & 15;
                *reinterpret_cast<uint4*>(sm5 + SM_A + row * L5_STRIDE + c * 16) = ap[s];
            }
        }
        __syncthreads();

        float acc[2][4][4];
#pragma unroll
        for (int mi = 0; mi < 2; ++mi)
#pragma unroll
            for (int nf = 0; nf < 4; ++nf)
#pragma unroll
                for (int j = 0; j < 4; ++j) acc[mi][nf][j] = 0.0f;

#pragma unroll
        for (int ks = 0; ks < 8; ++ks) {
            uint32_t a[2][4], b[2][4];
#pragma unroll
            for (int mi = 0; mi < 2; ++mi)
                ldm4(a[mi], aBase + mi * 16 * L5_STRIDE + ks * 32);
#pragma unroll
            for (int nj = 0; nj < 2; ++nj)
                ldm4(b[nj], bBase + nj * 16 * L5_STRIDE + ks * 32);
#pragma unroll
            for (int mi = 0; mi < 2; ++mi)
#pragma unroll
                for (int nf = 0; nf < 4; ++nf)
                    mma_f16(acc[mi][nf], a[mi],
                            b[nf >> 1][(nf & 1) * 2], b[nf >> 1][(nf & 1) * 2 + 1]);
        }

        // stage 64x128 tile (+bias) into dedicated region; accumulate stats
#pragma unroll
        for (int mi = 0; mi < 2; ++mi) {
            int rl = m0 + mi * 16 + (lane >> 2);
#pragma unroll
            for (int nf = 0; nf < 4; ++nf) {
                int cl = n0 + nf * 8 + (lane & 3) * 2;
                float b0 = sbias[cl], b1 = sbias[cl + 1];
                float c0 = acc[mi][nf][0] + b0, c1 = acc[mi][nf][1] + b1;
                float c2 = acc[mi][nf][2] + b0, c3 = acc[mi][nf][3] + b1;
                stag[rl * 132 + cl] = c0;       stag[rl * 132 + cl + 1] = c1;
                stag[(rl + 8) * 132 + cl] = c2; stag[(rl + 8) * 132 + cl + 1] = c3;
                s1[nf][0] += c0 + c2;           s1[nf][1] += c1 + c3;
                s2[nf][0] += c0 * c0 + c2 * c2; s2[nf][1] += c1 * c1 + c3 * c3;
            }
        }
        __syncthreads();

        // per-molecule max/min scan -> head/tail buffers (no atomics; molecule id GLOBAL)
        int bStart = rowCta / PLEN, bEnd = (rowCta + 63) / PLEN;
        int nm = bEnd - bStart + 1;
        for (int tk = tid; tk < nm * 128; tk += 256) {
            int bi = tk >> 7, c = tk & 127;
            int b = bStart + bi;
            int r0 = b * PLEN - rowCta, r1 = r0 + PLEN;
            int a0 = r0 > 0 ? r0 : 0, a1 = r1 < 64 ? r1 : 64;
            float mx = -FLT_MAX, mn = FLT_MAX;
            for (int r = a0; r < a1; ++r) {
                float v = stag[r * 132 + c];
                mx = fmaxf(mx, v); mn = fminf(mn, v);
            }
            size_t gi = (size_t)b * 1024 + colBase + c;
            if (r0 >= 0) { g_mxH[gi] = mx; g_mnH[gi] = mn; }
            else         { g_mxT[gi] = mx; g_mnT[gi] = mn; }
        }
    }

    // stats atomics once per CTA (accumulated over all 8 subtiles)
#pragma unroll
    for (int nf = 0; nf < 4; ++nf)
#pragma unroll
        for (int j = 0; j < 2; ++j) {
            float v1 = s1[nf][j], v2 = s2[nf][j];
            v1 += __shfl_xor_sync(0xffffffffu, v1, 4);
            v1 += __shfl_xor_sync(0xffffffffu, v1, 8);
            v1 += __shfl_xor_sync(0xffffffffu, v1, 16);
            v2 += __shfl_xor_sync(0xffffffffu, v2, 4);
            v2 += __shfl_xor_sync(0xffffffffu, v2, 8);
            v2 += __shfl_xor_sync(0xffffffffu, v2, 16);
            if (lane < 4) {
                int col = colBase + n0 + nf * 8 + lane * 2 + j;
                atomicAdd(&g_sum[tw][4][col], v1);
                atomicAdd(&g_sq [tw][4][col], v2);
            }
        }
}

// ---------------- max-pool (partials) + inline BN affine + embedding, both towers ----------------
__global__ void __launch_bounds__(256)
maxpool_embed_kernel(const float* __restrict__ embW, const float* __restrict__ embB,
                     const float* __restrict__ gamma, const float* __restrict__ beta,
                     float* __restrict__ out) {
    int bg = blockIdx.x;              // global molecule 0..2*BATCH-1
    int tw = bg >> 12, bl = bg & (BATCH - 1);
    int tid = threadIdx.x;
    int sCta = (bg * PLEN) / 64, eCta = (bg * PLEN + PLEN - 1) / 64;
    bool split = sCta != eCta;
    __shared__ float sE[10];
    if (tid < 10) sE[tid] = 0.0f;
    __syncthreads();
    float acc[10];
#pragma unroll
    for (int j = 0; j < 10; ++j) acc[j] = 0.0f;
    const float invN = 1.0f / (float)N_NODES;
    for (int cc = tid; cc < 1024; cc += 256) {
        size_t gi = (size_t)bg * 1024 + cc;
        float mx = g_mxH[gi], mn = g_mnH[gi];
        if (split) {
            mx = fmaxf(mx, g_mxT[gi]);
            mn = fminf(mn, g_mnT[gi]);
        }
        float mu  = g_sum[tw][4][cc] * invN;
        float var = g_sq[tw][4][cc] * invN - mu * mu;
        float a = gamma[cc] * rsqrtf(var + BN_EPS);
        float d = beta[cc] - mu * a;
        float pooled = fmaxf(fmaxf(fmaf(a, mx, d), fmaf(a, mn, d)), 0.0f);
#pragma unroll
        for (int j = 0; j < 10; ++j)
            acc[j] = fmaf(pooled, embW[cc * 10 + j], acc[j]);
    }
#pragma unroll
    for (int j = 0; j < 10; ++j) {
        float v = acc[j];
        for (int off = 16; off; off >>= 1) v += __shfl_down_sync(0xffffffffu, v, off);
        if ((tid & 31) == 0) atomicAdd(&sE[j], v);
    }
    __syncthreads();
    if (tid < 10) {
        float e = sE[tid] + embB[tid];
        out[(tw ? O_E2 : O_E1) + bl * 10 + tid] = e;
        g_e[tw][bl * 10 + tid] = e;
    }
}

// ---------------- cluster assignment (4 molecules per block, both towers) ----------------
__global__ void __launch_bounds__(256)
cluster_kernel(const float* __restrict__ clu, float* __restrict__ out) {
    int tid = threadIdx.x;
    __shared__ float sclu[8000];
    __shared__ float se[10];
    __shared__ float squn[800];
    __shared__ float sred[9];
    for (int s = tid; s < 8000; s += 256) sclu[s] = clu[s];
    for (int bb = 0; bb < 4; ++bb) {
        int bg = blockIdx.x * 4 + bb;
        int tw = bg >> 12, bl = bg & (BATCH - 1);
        float* qo = out + (tw ? O_C2 : O_C1) + (size_t)bl * 800;
        float* dq = (tw == 0) ? out + O_D1 + (size_t)bl * 800 : (float*)0;
        __syncthreads();
        if (tid < 10) se[tid] = g_e[tw][bl * 10 + tid];
        __syncthreads();
        float local = 0.0f;
        for (int j = tid; j < 800; j += 256) {
            float dist = 0.0f;
#pragma unroll
            for (int k = 0; k < 10; ++k) {
                float t = se[k] - sclu[j * 10 + k];
                dist = fmaf(t, t, dist);
            }
            float qun = 1.0f / (1.0f + dist);
            squn[j] = qun; local += qun;
            if (dq) dq[j] = dist;
        }
        float v = local;
        for (int off = 16; off; off >>= 1) v += __shfl_down_sync(0xffffffffu, v, off);
        if ((tid & 31) == 0) sred[tid >> 5] = v;
        __syncthreads();
        if (tid == 0) {
            float t = 0.f;
            for (int w = 0; w < 8; ++w) t += sred[w];
            sred[8] = 1.0f / t;
        }
        __syncthreads();
        float inv = sred[8];
        for (int j = tid; j < 800; j += 256)
            qo[j] = squn[j] * inv;
    }
}

// ---------------- pairwise distance ----------------
__global__ void sim_kernel(float* __restrict__ simOut) {
    int i = blockIdx.x * blockDim.x + threadIdx.x;
    if (i >= BATCH) return;
    float s = 0.0f;
#pragma unroll
    for (int k = 0; k < 10; ++k) {
        float t = g_e[0][i * 10 + k] - g_e[1][i * 10 + k] + 1e-6f;
        s = fmaf(t, t, s);
    }
    simOut[i] = sqrtf(s);
}

// ---------------- launch ----------------
extern "C" void kernel_launch(void* const* d_in, const int* in_sizes, int n_in,
                              void* d_out, int out_size) {
    const float* x1 = (const float*)d_in[0];
    const float* x2 = (const float*)d_in[1];
    const float* W[5]; const float* bb[5]; const float* gam[5]; const float* bet[5];
    for (int li = 0; li < 5; ++li) {
        W[li]   = (const float*)d_in[2 + li * 4 + 0];
        bb[li]  = (const float*)d_in[2 + li * 4 + 1];
        gam[li] = (const float*)d_in[2 + li * 4 + 2];
        bet[li] = (const float*)d_in[2 + li * 4 + 3];
    }
    const float* embW = (const float*)d_in[22];
    const float* embB = (const float*)d_in[23];
    const float* clu  = (const float*)d_in[24];
    float* out = (float*)d_out;

    const int SMEM64  = (64 * 132 + 64 * 64  + 2 * 64) * 4;  // 50688
    const int SMEM128 = (64 * 132 + 64 * 128 + 2 * 64) * 4;  // 67072
    cudaFuncSetAttribute((const void*)gcn_gemm<64, 64>,
                         cudaFuncAttributeMaxDynamicSharedMemorySize, SMEM64);
    cudaFuncSetAttribute((const void*)gcn_gemm<64, 128>,
                         cudaFuncAttributeMaxDynamicSharedMemorySize, SMEM128);
    cudaFuncSetAttribute((const void*)layer5_mma,
                         cudaFuncAttributeMaxDynamicSharedMemorySize, SM_TOT);

    const int RT2 = TW2 / 128;   // 896 row tiles of 128

    prep_W5_kernel<<<512, 256>>>(W[4]);
    zero_stats_kernel<<<10, 1024>>>();
    layer1_kernel<<<TW2 / 64, 256>>>(x1, x2, W[0], bb[0]);
    gcn_gemm<64, 64><<<dim3(RT2, 1), 256, SMEM64>>>(W[1], bb[1], 0, 1,
                                                    gam[0], bet[0], 0, 1, 64);
    gcn_gemm<64, 64><<<dim3(RT2, 1), 256, SMEM64>>>(W[2], bb[2], 1, 0,
                                                    gam[1], bet[1], 1, 2, 64);
    gcn_gemm<64, 128><<<dim3(RT2, 1), 256, SMEM128>>>(W[3], bb[3], 0, 1,
                                                      gam[2], bet[2], 2, 3, 128);
    prep_A5_kernel<<<RT2, 256>>>(gam[3], bet[3]);
    layer5_mma<<<dim3(8, TW2 / 512), 256, SM_TOT>>>(bb[4]);
    maxpool_embed_kernel<<<2 * BATCH, 256>>>(embW, embB, gam[4], bet[4], out);
    cluster_kernel<<<2 * BATCH / 4, 256>>>(clu, out);
    sim_kernel<<<16, 256>>>(out);
}